// round 1
// baseline (speedup 1.0000x reference)
#include <cuda_runtime.h>
#include <math.h>

// Problem constants
#define BSZ   64
#define NTOK  1024
#define MCH   64
#define DCH   256       // 4*M
#define PDIM  64
#define RTOT  (BSZ*NTOK)   // 65536
#define HMAX  360
#define EPSF  1e-5f
#define NBLK_RL (RTOT/8)   // 8192 reg_linear blocks

// -------- scratch (static __device__ globals; no runtime allocation) --------
__device__ __align__(16) float g_h[(size_t)RTOT*DCH];          // 64 MB  [B,N,256]
__device__ __align__(16) float g_y[(size_t)RTOT*DCH];          // 64 MB  [B,N,256]
__device__ __align__(16) float g_q[(size_t)BSZ*HMAX*NTOK];     // 90 MB  [B,H,N]
__device__ __align__(16) float g_kv[(size_t)BSZ*HMAX*NTOK];    // 90 MB  [B,H,N]
__device__ __align__(16) float2 g_Ff[HMAX*NTOK];               // filter spectra [H][N]
__device__ float g_part0[MCH*NBLK_RL];                          // BN partial sums (s^2)
__device__ float g_part1[MCH*NBLK_RL];                          // BN partial sums (|v|^2)
__device__ float g_scale0[MCH];
__device__ float g_scale1[MCH];

// ---------------------------------------------------------------------------
// init: h[b,n,4m+0] = (pe(n)+tok_emb[tt]) @ Wf,  h[b,n,4m+1+d] = x[b,n,d]*wv[m]
// ---------------------------------------------------------------------------
__global__ void init_h_kernel(const float* __restrict__ x,
                              const float* __restrict__ tok_emb,
                              const float* __restrict__ Wf,
                              const float* __restrict__ wv)
{
    int n = blockIdx.x;
    int tid = threadIdx.x;   // 256
    __shared__ float f[PDIM];
    __shared__ float s0[MCH];
    if (tid < PDIM) {
        int p = tid;
        int j2 = p & ~1;
        float div = expf(-logf(10000.0f) * (float)j2 / (float)PDIM);
        float ang = (float)n * div;
        float pe = (p & 1) ? cosf(ang) : sinf(ang);
        int tt = (n == NTOK - 1) ? 2 : (n & 1);
        f[p] = pe + tok_emb[tt * PDIM + p];
    }
    __syncthreads();
    if (tid < MCH) {
        float acc = 0.f;
        #pragma unroll 8
        for (int p = 0; p < PDIM; p++) acc += f[p] * Wf[p * MCH + tid];
        s0[tid] = acc;
    }
    __syncthreads();
    int m = tid >> 2, r = tid & 3;
    float wvm = wv[m];
    float sv = s0[m];
    for (int b = 0; b < BSZ; b++) {
        float val;
        if (r == 0) val = sv;
        else        val = x[((size_t)b * NTOK + n) * 3 + (r - 1)] * wvm;
        g_h[((size_t)b * NTOK + n) * DCH + tid] = val;
    }
}

// ---------------------------------------------------------------------------
// Fused q/k/v GEMM: A = g_h [R,256], W* [256,H].
// Writes Q = A@Wq and KV = (A@Wk)*(A@Wv) in [B,H,N] layout (transposed).
// 64x64 tile, 256 threads, 4x4 microtile, k-step 16.
// ---------------------------------------------------------------------------
__global__ void __launch_bounds__(256) gemm_qkv(const float* __restrict__ Wq,
                                                const float* __restrict__ Wk,
                                                const float* __restrict__ Wv2,
                                                int H)
{
    int row0 = blockIdx.y * 64;
    int col0 = blockIdx.x * 64;
    int b = row0 >> 10;
    int nbase = row0 & (NTOK - 1);

    __shared__ __align__(16) float As[16][68];
    __shared__ __align__(16) float Bq[16][68];
    __shared__ __align__(16) float Bk[16][68];
    __shared__ __align__(16) float Bv[16][68];

    int tid = threadIdx.x;
    int tx = tid & 15, ty = tid >> 4;
    int lrow = tid >> 2, lkq = tid & 3;     // A-tile loader mapping
    int wk = tid >> 4, wseg = tid & 15;     // W-tile loader mapping
    bool fullcol = (col0 + 64 <= H);

    float aq[4][4] = {}, ak[4][4] = {}, av[4][4] = {};

    for (int k0 = 0; k0 < DCH; k0 += 16) {
        float4 a4 = *(const float4*)&g_h[(size_t)(row0 + lrow) * DCH + k0 + lkq * 4];
        As[lkq * 4 + 0][lrow] = a4.x;
        As[lkq * 4 + 1][lrow] = a4.y;
        As[lkq * 4 + 2][lrow] = a4.z;
        As[lkq * 4 + 3][lrow] = a4.w;
        if (fullcol) {
            size_t o = (size_t)(k0 + wk) * H + col0 + wseg * 4;
            *(float4*)&Bq[wk][wseg * 4] = *(const float4*)&Wq[o];
            *(float4*)&Bk[wk][wseg * 4] = *(const float4*)&Wk[o];
            *(float4*)&Bv[wk][wseg * 4] = *(const float4*)&Wv2[o];
        } else {
            #pragma unroll
            for (int c = 0; c < 4; c++) {
                int col = col0 + wseg * 4 + c;
                float vq = 0.f, vk = 0.f, vv = 0.f;
                if (col < H) {
                    size_t o = (size_t)(k0 + wk) * H + col;
                    vq = Wq[o]; vk = Wk[o]; vv = Wv2[o];
                }
                Bq[wk][wseg * 4 + c] = vq;
                Bk[wk][wseg * 4 + c] = vk;
                Bv[wk][wseg * 4 + c] = vv;
            }
        }
        __syncthreads();
        #pragma unroll
        for (int kk = 0; kk < 16; kk++) {
            float4 a  = *(float4*)&As[kk][ty * 4];
            float4 bq = *(float4*)&Bq[kk][tx * 4];
            float4 bk = *(float4*)&Bk[kk][tx * 4];
            float4 bv = *(float4*)&Bv[kk][tx * 4];
            float ar[4]  = {a.x, a.y, a.z, a.w};
            float bqr[4] = {bq.x, bq.y, bq.z, bq.w};
            float bkr[4] = {bk.x, bk.y, bk.z, bk.w};
            float bvr[4] = {bv.x, bv.y, bv.z, bv.w};
            #pragma unroll
            for (int i = 0; i < 4; i++)
                #pragma unroll
                for (int j = 0; j < 4; j++) {
                    aq[i][j] += ar[i] * bqr[j];
                    ak[i][j] += ar[i] * bkr[j];
                    av[i][j] += ar[i] * bvr[j];
                }
        }
        __syncthreads();
    }
    #pragma unroll
    for (int j = 0; j < 4; j++) {
        int col = col0 + tx * 4 + j;
        if (col < H) {
            size_t base = ((size_t)b * H + col) * NTOK + nbase + ty * 4;
            *(float4*)&g_q[base] = make_float4(aq[0][j], aq[1][j], aq[2][j], aq[3][j]);
            *(float4*)&g_kv[base] = make_float4(ak[0][j] * av[0][j], ak[1][j] * av[1][j],
                                                ak[2][j] * av[2][j], ak[3][j] * av[3][j]);
        }
    }
}

// ---------------------------------------------------------------------------
// 1024-point complex FFT in shared memory, 256 threads. dir=-1 fwd, +1 inv.
// ---------------------------------------------------------------------------
__device__ __forceinline__ void block_fft(float2* s, int tid, float dir)
{
    // bit-reverse permutation (pairs are disjoint; only i<j thread swaps)
    for (int i = tid; i < 1024; i += 256) {
        int j = __brev(i) >> 22;
        if (j > i) { float2 t = s[i]; s[i] = s[j]; s[j] = t; }
    }
    __syncthreads();
    #pragma unroll
    for (int st = 1; st <= 10; st++) {
        int half = 1 << (st - 1);
        float base = dir * 6.283185307179586f / (float)(1 << st);
        #pragma unroll
        for (int t = tid; t < 512; t += 256) {
            int pos = t & (half - 1);
            int grp = t >> (st - 1);
            int i0 = (grp << st) + pos;
            float ang = base * (float)pos;
            float sn, cs;
            sincosf(ang, &sn, &cs);
            float2 u = s[i0];
            float2 w = s[i0 + half];
            float wr = w.x * cs - w.y * sn;
            float wi = w.x * sn + w.y * cs;
            s[i0]        = make_float2(u.x + wr, u.y + wi);
            s[i0 + half] = make_float2(u.x - wr, u.y - wi);
        }
        __syncthreads();
    }
}

__global__ void fft_filt_kernel(const float* __restrict__ filt, int H)
{
    int h = blockIdx.x;
    int tid = threadIdx.x;
    __shared__ float2 buf[1024];
    for (int n = tid; n < 1024; n += 256)
        buf[n] = make_float2(filt[(size_t)n * H + h], 0.f);
    __syncthreads();
    block_fft(buf, tid, -1.f);
    for (int f = tid; f < 1024; f += 256)
        g_Ff[h * 1024 + f] = buf[f];
}

// per-(b,h): g = q * Re(IFFT(FFT(k*v) .* FFT(filt))); overwrites g_q in place
__global__ void conv_kernel(int H)
{
    int h = blockIdx.x, b = blockIdx.y;
    int tid = threadIdx.x;
    __shared__ float2 buf[1024];
    const float* kvp = &g_kv[((size_t)b * H + h) * NTOK];
    float* qp = &g_q[((size_t)b * H + h) * NTOK];
    for (int n = tid; n < 1024; n += 256)
        buf[n] = make_float2(kvp[n], 0.f);
    __syncthreads();
    block_fft(buf, tid, -1.f);
    for (int f = tid; f < 1024; f += 256) {
        float2 a = buf[f];
        float2 c = g_Ff[h * 1024 + f];
        buf[f] = make_float2(a.x * c.x - a.y * c.y, a.x * c.y + a.y * c.x);
    }
    __syncthreads();
    block_fft(buf, tid, 1.f);
    const float inv = 1.f / 1024.f;
    for (int n = tid; n < 1024; n += 256)
        qp[n] = qp[n] * buf[n].x * inv;
}

// ---------------------------------------------------------------------------
// Wo GEMM with residual: g_h[R,256] += G([B,H,N] logical [R,H]) @ Wo[H,256]
// ---------------------------------------------------------------------------
__global__ void __launch_bounds__(256) gemm_out(const float* __restrict__ Wo, int H)
{
    int row0 = blockIdx.y * 64;
    int col0 = blockIdx.x * 64;
    int b = row0 >> 10;
    int nbase = row0 & (NTOK - 1);

    __shared__ __align__(16) float As[16][68];
    __shared__ __align__(16) float Ws[16][68];
    int tid = threadIdx.x;
    int tx = tid & 15, ty = tid >> 4;
    int wk = tid >> 4, wseg = tid & 15;
    float acc[4][4] = {};

    for (int k0 = 0; k0 < H; k0 += 16) {
        float4 va = make_float4(0.f, 0.f, 0.f, 0.f);
        float4 vw = make_float4(0.f, 0.f, 0.f, 0.f);
        if (k0 + wk < H) {
            va = *(const float4*)&g_q[((size_t)b * H + k0 + wk) * NTOK + nbase + wseg * 4];
            vw = *(const float4*)&Wo[(size_t)(k0 + wk) * DCH + col0 + wseg * 4];
        }
        *(float4*)&As[wk][wseg * 4] = va;
        *(float4*)&Ws[wk][wseg * 4] = vw;
        __syncthreads();
        #pragma unroll
        for (int kk = 0; kk < 16; kk++) {
            float4 a = *(float4*)&As[kk][ty * 4];
            float4 w = *(float4*)&Ws[kk][tx * 4];
            float ar[4] = {a.x, a.y, a.z, a.w};
            float br[4] = {w.x, w.y, w.z, w.w};
            #pragma unroll
            for (int i = 0; i < 4; i++)
                #pragma unroll
                for (int j = 0; j < 4; j++)
                    acc[i][j] += ar[i] * br[j];
        }
        __syncthreads();
    }
    #pragma unroll
    for (int i = 0; i < 4; i++) {
        int row = row0 + ty * 4 + i;
        float4* hp = (float4*)&g_h[(size_t)row * DCH + col0 + tx * 4];
        float4 hv = *hp;
        hv.x += acc[i][0]; hv.y += acc[i][1]; hv.z += acc[i][2]; hv.w += acc[i][3];
        *hp = hv;
    }
}

// ---------------------------------------------------------------------------
// reg_linear: y = degree-wise mix across multiplicity; also emit BN partials.
// 8 tokens/block, 256 threads (k = tid&63, group = tid>>6 handles 2 tokens).
// ---------------------------------------------------------------------------
__global__ void __launch_bounds__(256) reglin_kernel(const float* __restrict__ Wm0,
                                                     const float* __restrict__ Wm1)
{
    __shared__ float W0[64 * 64];
    __shared__ float W1[64 * 64];
    __shared__ __align__(16) float hs[8 * 256];
    __shared__ float red0[256], red1[256];
    int tid = threadIdx.x;
    int row0 = blockIdx.x * 8;
    for (int i = tid; i < 4096; i += 256) { W0[i] = Wm0[i]; W1[i] = Wm1[i]; }
    for (int i = tid; i < 2048; i += 256) hs[i] = g_h[(size_t)row0 * DCH + i];
    __syncthreads();
    int k = tid & 63, grp = tid >> 6;
    float ls0 = 0.f, ls1 = 0.f;
    #pragma unroll
    for (int tt = 0; tt < 2; tt++) {
        int t = grp * 2 + tt;
        const float* hr = &hs[t * 256];
        float s = 0.f, v0 = 0.f, v1 = 0.f, v2 = 0.f;
        #pragma unroll 8
        for (int m = 0; m < 64; m++) {
            float4 hv = *(const float4*)&hr[m * 4];
            float w0 = W0[m * 64 + k];
            float w1 = W1[m * 64 + k];
            s  += hv.x * w0;
            v0 += hv.y * w1;
            v1 += hv.z * w1;
            v2 += hv.w * w1;
        }
        *(float4*)&g_y[(size_t)(row0 + t) * DCH + k * 4] = make_float4(s, v0, v1, v2);
        ls0 += s * s;
        ls1 += v0 * v0 + v1 * v1 + v2 * v2;
    }
    red0[tid] = ls0; red1[tid] = ls1;
    __syncthreads();
    if (grp == 0) {
        float t0 = red0[k] + red0[64 + k] + red0[128 + k] + red0[192 + k];
        float t1 = red1[k] + red1[64 + k] + red1[128 + k] + red1[192 + k];
        g_part0[k * NBLK_RL + blockIdx.x] = t0;
        g_part1[k * NBLK_RL + blockIdx.x] = t1;
    }
}

// deterministic reduction of BN partials -> per-channel scales
__global__ void scale_red_kernel(const float* __restrict__ g0, const float* __restrict__ g1)
{
    int c = blockIdx.x;          // 0..127
    int ch = c & 63;
    const float* src = (c < 64) ? &g_part0[(size_t)ch * NBLK_RL] : &g_part1[(size_t)ch * NBLK_RL];
    int tid = threadIdx.x;
    float s = 0.f;
    for (int i = tid; i < NBLK_RL; i += 256) s += src[i];
    __shared__ float red[256];
    red[tid] = s;
    __syncthreads();
    for (int st = 128; st; st >>= 1) {
        if (tid < st) red[tid] += red[tid + st];
        __syncthreads();
    }
    if (tid == 0) {
        float norm = sqrtf(red[0] / (float)RTOT + EPSF);
        if (c < 64) g_scale0[ch] = g0[ch] / norm;
        else        g_scale1[ch] = g1[ch] / norm;
    }
}

// BN scale + norm activation + residual: h += act(bn(y))
__global__ void actres_kernel()
{
    size_t idx = (size_t)blockIdx.x * 256 + threadIdx.x;   // over RTOT*64 irreps
    int m = (int)(idx & 63);
    float4 yv = *(float4*)&g_y[idx * 4];
    float s  = yv.x * g_scale0[m];
    float sc = g_scale1[m];
    float v0 = yv.y * sc, v1 = yv.z * sc, v2 = yv.w * sc;
    float sg  = 1.f / (1.f + __expf(-fabsf(s)));
    float vn  = sqrtf(v0 * v0 + v1 * v1 + v2 * v2 + EPSF);
    float sgv = 1.f / (1.f + __expf(-vn));
    float4* hp = (float4*)&g_h[idx * 4];
    float4 hv = *hp;
    hv.x += s * sg;
    hv.y += v0 * sgv;
    hv.z += v1 * sgv;
    hv.w += v2 * sgv;
    *hp = hv;
}

// final: out[b,d] = (1/N) sum_n sum_m h[b,n,4m+1+d] * w_out[m]
__global__ void pool_kernel(const float* __restrict__ w_out, float* __restrict__ out)
{
    int b = blockIdx.x;
    int tid = threadIdx.x;   // 256
    __shared__ float wsh[64];
    if (tid < 64) wsh[tid] = w_out[tid];
    __syncthreads();
    float a0 = 0.f, a1 = 0.f, a2 = 0.f;
    for (int n = tid; n < NTOK; n += 256) {
        const float* hr = &g_h[((size_t)b * NTOK + n) * DCH];
        #pragma unroll 8
        for (int m = 0; m < 64; m++) {
            float w = wsh[m];
            float4 hv = *(const float4*)&hr[m * 4];
            a0 += hv.y * w;
            a1 += hv.z * w;
            a2 += hv.w * w;
        }
    }
    __shared__ float r0[256], r1[256], r2[256];
    r0[tid] = a0; r1[tid] = a1; r2[tid] = a2;
    __syncthreads();
    for (int st = 128; st; st >>= 1) {
        if (tid < st) { r0[tid] += r0[tid + st]; r1[tid] += r1[tid + st]; r2[tid] += r2[tid + st]; }
        __syncthreads();
    }
    if (tid == 0) {
        out[b * 3 + 0] = r0[0] / (float)NTOK;
        out[b * 3 + 1] = r1[0] / (float)NTOK;
        out[b * 3 + 2] = r2[0] / (float)NTOK;
    }
}

// ---------------------------------------------------------------------------
extern "C" void kernel_launch(void* const* d_in, const int* in_sizes, int n_in,
                              void* d_out, int out_size)
{
    (void)in_sizes; (void)n_in; (void)out_size;
    const float* x       = (const float*)d_in[0];
    const float* tok_emb = (const float*)d_in[1];
    const float* Wf      = (const float*)d_in[2];
    const float* wv      = (const float*)d_in[3];
    const float* w_out   = (const float*)d_in[4];
    const int Hs[3] = {360, 360, 160};

    init_h_kernel<<<NTOK, 256>>>(x, tok_emb, Wf, wv);

    for (int L = 0; L < 3; L++) {
        int base = 5 + L * 9;
        const float* Wq   = (const float*)d_in[base + 0];
        const float* Wk   = (const float*)d_in[base + 1];
        const float* Wvw  = (const float*)d_in[base + 2];
        const float* filt = (const float*)d_in[base + 3];
        const float* Wo   = (const float*)d_in[base + 4];
        const float* Wm0  = (const float*)d_in[base + 5];
        const float* Wm1  = (const float*)d_in[base + 6];
        const float* g0   = (const float*)d_in[base + 7];
        const float* g1   = (const float*)d_in[base + 8];
        int H = Hs[L];

        gemm_qkv<<<dim3((H + 63) / 64, RTOT / 64), 256>>>(Wq, Wk, Wvw, H);
        fft_filt_kernel<<<H, 256>>>(filt, H);
        conv_kernel<<<dim3(H, BSZ), 256>>>(H);
        gemm_out<<<dim3(DCH / 64, RTOT / 64), 256>>>(Wo, H);
        reglin_kernel<<<NBLK_RL, 256>>>(Wm0, Wm1);
        scale_red_kernel<<<128, 256>>>(g0, g1);
        actres_kernel<<<RTOT * 64 / 256, 256>>>();
    }

    pool_kernel<<<BSZ, 256>>>(w_out, (float*)d_out);
}

// round 3
// speedup vs baseline: 1.2390x; 1.2390x over previous
#include <cuda_runtime.h>
#include <math.h>
#include <stdint.h>

// Problem constants
#define BSZ   64
#define NTOK  1024
#define MCH   64
#define DCH   256       // 4*M
#define PDIM  64
#define RTOT  (BSZ*NTOK)   // 65536
#define HMAX  360
#define EPSF  1e-5f
#define NBLK_RL (RTOT/8)   // 8192 reg_linear blocks

// -------- scratch (static __device__ globals; no runtime allocation) --------
__device__ __align__(16) float g_h[(size_t)RTOT*DCH];          // [B,N,256]
__device__ __align__(16) float g_y[(size_t)RTOT*DCH];          // [B,N,256]
__device__ __align__(16) float g_q[(size_t)BSZ*HMAX*NTOK];     // [B,H,N]
__device__ __align__(16) float g_kv[(size_t)BSZ*HMAX*NTOK];    // [B,H,N]
__device__ __align__(16) float2 g_Ff[HMAX*NTOK];               // filter spectra [H][N]
__device__ float g_part0[MCH*NBLK_RL];
__device__ float g_part1[MCH*NBLK_RL];
__device__ float g_scale0[MCH];
__device__ float g_scale1[MCH];

// ---------------------------------------------------------------------------
__device__ __forceinline__ void mma_tf32(float* c, const uint32_t* a, const uint32_t* b)
{
    asm volatile(
        "mma.sync.aligned.m16n8k8.row.col.f32.tf32.tf32.f32 "
        "{%0,%1,%2,%3}, {%4,%5,%6,%7}, {%8,%9}, {%0,%1,%2,%3};\n"
        : "+f"(c[0]), "+f"(c[1]), "+f"(c[2]), "+f"(c[3])
        : "r"(a[0]), "r"(a[1]), "r"(a[2]), "r"(a[3]), "r"(b[0]), "r"(b[1]));
}

__device__ __forceinline__ uint32_t tf32_rna(float x)
{
    uint32_t r;
    asm("cvt.rna.tf32.f32 %0, %1;" : "=r"(r) : "f"(x));
    return r;
}
// split x into hi (tf32, RN) and lo = x - hi (fp32 exact)
__device__ __forceinline__ void tf32_split(float x, uint32_t& hi, uint32_t& lo)
{
    hi = tf32_rna(x);
    lo = __float_as_uint(x - __uint_as_float(hi));
}

// ---------------------------------------------------------------------------
// init: h[b,n,4m+0] = (pe(n)+tok_emb[tt]) @ Wf,  h[b,n,4m+1+d] = x[b,n,d]*wv[m]
// ---------------------------------------------------------------------------
__global__ void init_h_kernel(const float* __restrict__ x,
                              const float* __restrict__ tok_emb,
                              const float* __restrict__ Wf,
                              const float* __restrict__ wv)
{
    int n = blockIdx.x;
    int tid = threadIdx.x;   // 256
    __shared__ float f[PDIM];
    __shared__ float s0[MCH];
    if (tid < PDIM) {
        int p = tid;
        int j2 = p & ~1;
        float div = expf(-logf(10000.0f) * (float)j2 / (float)PDIM);
        float ang = (float)n * div;
        float pe = (p & 1) ? cosf(ang) : sinf(ang);
        int tt = (n == NTOK - 1) ? 2 : (n & 1);
        f[p] = pe + tok_emb[tt * PDIM + p];
    }
    __syncthreads();
    if (tid < MCH) {
        float acc = 0.f;
        #pragma unroll 8
        for (int p = 0; p < PDIM; p++) acc += f[p] * Wf[p * MCH + tid];
        s0[tid] = acc;
    }
    __syncthreads();
    int m = tid >> 2, r = tid & 3;
    float wvm = wv[m];
    float sv = s0[m];
    for (int b = 0; b < BSZ; b++) {
        float val;
        if (r == 0) val = sv;
        else        val = x[((size_t)b * NTOK + n) * 3 + (r - 1)] * wvm;
        g_h[((size_t)b * NTOK + n) * DCH + tid] = val;
    }
}

// ---------------------------------------------------------------------------
// Fused q/k/v GEMM via 3xTF32 mma.sync. A = g_h [R,256], W* [256,H].
// Block 256 thr, tile 64 rows x 64 cols, kstep 32. Warp grid 2x4,
// warp tile 32x16 (mfrags=2, nfrags=2) x 3 matrices.
// Writes Q = A@Wq and KV = (A@Wk)*(A@Wv) in [B,H,N] layout.
// ---------------------------------------------------------------------------
__global__ void __launch_bounds__(256) gemm_qkv(const float* __restrict__ Wq,
                                                const float* __restrict__ Wk,
                                                const float* __restrict__ Wv2,
                                                int H)
{
    int row0 = blockIdx.y * 64;
    int col0 = blockIdx.x * 64;
    int b = row0 >> 10;
    int nbase = row0 & (NTOK - 1);

    __shared__ __align__(16) float As[64][36];    // [row][k]
    __shared__ __align__(16) float Bq[32][68];    // [k][n]
    __shared__ __align__(16) float Bk[32][68];
    __shared__ __align__(16) float Bv[32][68];

    int tid = threadIdx.x;
    int wid = tid >> 5, lane = tid & 31;
    int g = lane >> 2, t = lane & 3;
    int wr = wid >> 2, wc = wid & 3;

    float accq[2][2][4] = {}, acck[2][2][4] = {}, accv[2][2][4] = {};

    for (int k0 = 0; k0 < DCH; k0 += 32) {
        // load A: 64x32 floats = 512 float4, 2 per thread
        #pragma unroll
        for (int i = 0; i < 2; i++) {
            int idx = tid + i * 256;
            int row = idx >> 3, kq = idx & 7;
            float4 a4 = *(const float4*)&g_h[(size_t)(row0 + row) * DCH + k0 + kq * 4];
            *(float4*)&As[row][kq * 4] = a4;
        }
        // load B tiles: 32x64 each = 512 float4, 2 per thread per matrix
        #pragma unroll
        for (int i = 0; i < 2; i++) {
            int idx = tid + i * 256;
            int kr = idx >> 4, nq = idx & 15;
            int col = col0 + nq * 4;
            float4 vq = make_float4(0.f,0.f,0.f,0.f), vk = vq, vv = vq;
            if (col + 3 < H) {
                size_t o = (size_t)(k0 + kr) * H + col;
                vq = *(const float4*)&Wq[o];
                vk = *(const float4*)&Wk[o];
                vv = *(const float4*)&Wv2[o];
            }
            *(float4*)&Bq[kr][nq * 4] = vq;
            *(float4*)&Bk[kr][nq * 4] = vk;
            *(float4*)&Bv[kr][nq * 4] = vv;
        }
        __syncthreads();
        #pragma unroll
        for (int ks = 0; ks < 4; ks++) {
            int kb = ks * 8;
            uint32_t ah[2][4], al[2][4];
            #pragma unroll
            for (int mf = 0; mf < 2; mf++) {
                int rb = wr * 32 + mf * 16;
                tf32_split(As[rb + g     ][kb + t    ], ah[mf][0], al[mf][0]);
                tf32_split(As[rb + g + 8 ][kb + t    ], ah[mf][1], al[mf][1]);
                tf32_split(As[rb + g     ][kb + t + 4], ah[mf][2], al[mf][2]);
                tf32_split(As[rb + g + 8 ][kb + t + 4], ah[mf][3], al[mf][3]);
            }
            #pragma unroll
            for (int nf = 0; nf < 2; nf++) {
                int nb = wc * 16 + nf * 8 + g;
                uint32_t bh[2], bl[2];
                // --- Q ---
                tf32_split(Bq[kb + t    ][nb], bh[0], bl[0]);
                tf32_split(Bq[kb + t + 4][nb], bh[1], bl[1]);
                #pragma unroll
                for (int mf = 0; mf < 2; mf++) {
                    mma_tf32(accq[mf][nf], ah[mf], bh);
                    mma_tf32(accq[mf][nf], ah[mf], bl);
                    mma_tf32(accq[mf][nf], al[mf], bh);
                }
                // --- K ---
                tf32_split(Bk[kb + t    ][nb], bh[0], bl[0]);
                tf32_split(Bk[kb + t + 4][nb], bh[1], bl[1]);
                #pragma unroll
                for (int mf = 0; mf < 2; mf++) {
                    mma_tf32(acck[mf][nf], ah[mf], bh);
                    mma_tf32(acck[mf][nf], ah[mf], bl);
                    mma_tf32(acck[mf][nf], al[mf], bh);
                }
                // --- V ---
                tf32_split(Bv[kb + t    ][nb], bh[0], bl[0]);
                tf32_split(Bv[kb + t + 4][nb], bh[1], bl[1]);
                #pragma unroll
                for (int mf = 0; mf < 2; mf++) {
                    mma_tf32(accv[mf][nf], ah[mf], bh);
                    mma_tf32(accv[mf][nf], ah[mf], bl);
                    mma_tf32(accv[mf][nf], al[mf], bh);
                }
            }
        }
        __syncthreads();
    }
    // epilogue: q and k*v to [B,H,N]
    #pragma unroll
    for (int mf = 0; mf < 2; mf++) {
        #pragma unroll
        for (int nf = 0; nf < 2; nf++) {
            #pragma unroll
            for (int cc = 0; cc < 2; cc++) {
                int col = col0 + wc * 16 + nf * 8 + t * 2 + cc;
                if (col < H) {
                    size_t base = ((size_t)b * H + col) * NTOK + nbase + wr * 32 + mf * 16 + g;
                    g_q[base]     = accq[mf][nf][cc];
                    g_q[base + 8] = accq[mf][nf][cc + 2];
                    g_kv[base]     = acck[mf][nf][cc]     * accv[mf][nf][cc];
                    g_kv[base + 8] = acck[mf][nf][cc + 2] * accv[mf][nf][cc + 2];
                }
            }
        }
    }
}

// ---------------------------------------------------------------------------
// Wo GEMM via 3xTF32 mma.sync + residual: g_h[R,256] += G[R,H] @ Wo[H,256]
// A read from g_q [B,H,N]. Block 256 thr, tile 128x128.
// ---------------------------------------------------------------------------
__global__ void __launch_bounds__(256) gemm_out(const float* __restrict__ Wo, int H)
{
    int row0 = blockIdx.y * 128;
    int col0 = blockIdx.x * 128;
    int b = row0 >> 10;
    int nbase = row0 & (NTOK - 1);

    __shared__ __align__(16) float As[32][136];   // [k][row]
    __shared__ __align__(16) float Bs[32][132];   // [k][n]

    int tid = threadIdx.x;
    int wid = tid >> 5, lane = tid & 31;
    int g = lane >> 2, t = lane & 3;
    int wr = wid >> 2, wc = wid & 3;              // warp tile 64x32

    float acc[4][4][4] = {};

    int ksteps = (H + 31) >> 5;
    for (int ki = 0; ki < ksteps; ki++) {
        int k0 = ki * 32;
        #pragma unroll
        for (int i = 0; i < 4; i++) {
            int idx = tid + i * 256;
            int k = idx >> 5, mq = idx & 31;
            float4 v = make_float4(0.f,0.f,0.f,0.f);
            if (k0 + k < H)
                v = *(const float4*)&g_q[((size_t)b * H + k0 + k) * NTOK + nbase + mq * 4];
            *(float4*)&As[k][mq * 4] = v;
        }
        #pragma unroll
        for (int i = 0; i < 4; i++) {
            int idx = tid + i * 256;
            int k = idx >> 5, nq = idx & 31;
            float4 v = make_float4(0.f,0.f,0.f,0.f);
            if (k0 + k < H)
                v = *(const float4*)&Wo[(size_t)(k0 + k) * DCH + col0 + nq * 4];
            *(float4*)&Bs[k][nq * 4] = v;
        }
        __syncthreads();
        #pragma unroll
        for (int ks = 0; ks < 4; ks++) {
            int kb = ks * 8;
            uint32_t ah[4][4], al[4][4];
            #pragma unroll
            for (int mf = 0; mf < 4; mf++) {
                int rb = wr * 64 + mf * 16;
                tf32_split(As[kb + t    ][rb + g    ], ah[mf][0], al[mf][0]);
                tf32_split(As[kb + t    ][rb + g + 8], ah[mf][1], al[mf][1]);
                tf32_split(As[kb + t + 4][rb + g    ], ah[mf][2], al[mf][2]);
                tf32_split(As[kb + t + 4][rb + g + 8], ah[mf][3], al[mf][3]);
            }
            #pragma unroll
            for (int nf = 0; nf < 4; nf++) {
                int nb = wc * 32 + nf * 8 + g;
                uint32_t bh[2], bl[2];
                tf32_split(Bs[kb + t    ][nb], bh[0], bl[0]);
                tf32_split(Bs[kb + t + 4][nb], bh[1], bl[1]);
                #pragma unroll
                for (int mf = 0; mf < 4; mf++) {
                    mma_tf32(acc[mf][nf], ah[mf], bh);
                    mma_tf32(acc[mf][nf], ah[mf], bl);
                    mma_tf32(acc[mf][nf], al[mf], bh);
                }
            }
        }
        __syncthreads();
    }
    #pragma unroll
    for (int mf = 0; mf < 4; mf++) {
        #pragma unroll
        for (int nf = 0; nf < 4; nf++) {
            int col = col0 + wc * 32 + nf * 8 + t * 2;
            #pragma unroll
            for (int rr = 0; rr < 2; rr++) {
                int row = row0 + wr * 64 + mf * 16 + g + rr * 8;
                float2* hp = (float2*)&g_h[(size_t)row * DCH + col];
                float2 hv = *hp;
                hv.x += acc[mf][nf][rr * 2];
                hv.y += acc[mf][nf][rr * 2 + 1];
                *hp = hv;
            }
        }
    }
}

// ---------------------------------------------------------------------------
// 1024-pt complex FFT in shared memory with twiddle table. 256 threads.
// ---------------------------------------------------------------------------
__device__ __forceinline__ void fft_build_tw(float2* tw, int tid)
{
    for (int k = tid; k < 512; k += 256) {
        float ang = -6.283185307179586f * (float)k / 1024.f;
        float sn, cs;
        sincosf(ang, &sn, &cs);
        tw[k] = make_float2(cs, sn);
    }
}

template<bool INV>
__device__ __forceinline__ void block_fft_t(float2* s, const float2* tw, int tid)
{
    for (int i = tid; i < 1024; i += 256) {
        int j = __brev(i) >> 22;
        if (j > i) { float2 tmp = s[i]; s[i] = s[j]; s[j] = tmp; }
    }
    __syncthreads();
    #pragma unroll
    for (int st = 1; st <= 10; st++) {
        int half = 1 << (st - 1);
        int shift = 10 - st;
        #pragma unroll
        for (int tt = tid; tt < 512; tt += 256) {
            int pos = tt & (half - 1);
            int grp = tt >> (st - 1);
            int i0 = (grp << st) + pos;
            float2 w = tw[pos << shift];
            float wy = INV ? -w.y : w.y;
            float2 u = s[i0];
            float2 v = s[i0 + half];
            float wr = v.x * w.x - v.y * wy;
            float wi = v.x * wy + v.y * w.x;
            s[i0]        = make_float2(u.x + wr, u.y + wi);
            s[i0 + half] = make_float2(u.x - wr, u.y - wi);
        }
        __syncthreads();
    }
}

__global__ void fft_filt_kernel(const float* __restrict__ filt, int H)
{
    int h = blockIdx.x;
    int tid = threadIdx.x;
    __shared__ float2 buf[1024];
    __shared__ float2 tw[512];
    fft_build_tw(tw, tid);
    for (int n = tid; n < 1024; n += 256)
        buf[n] = make_float2(filt[(size_t)n * H + h], 0.f);
    __syncthreads();
    block_fft_t<false>(buf, tw, tid);
    for (int f = tid; f < 1024; f += 256)
        g_Ff[h * 1024 + f] = buf[f];
}

// Packed-pair conv: two batch rows (same h) share one fwd + one inv FFT.
__global__ void conv_kernel(int H)
{
    int h = blockIdx.x;
    int b0 = blockIdx.y * 2, b1 = b0 + 1;
    int tid = threadIdx.x;
    __shared__ float2 bufA[1024];
    __shared__ float2 bufB[1024];
    __shared__ float2 tw[512];
    fft_build_tw(tw, tid);

    const float* kv0 = &g_kv[((size_t)b0 * H + h) * NTOK];
    const float* kv1 = &g_kv[((size_t)b1 * H + h) * NTOK];
    float* qp0 = &g_q[((size_t)b0 * H + h) * NTOK];
    float* qp1 = &g_q[((size_t)b1 * H + h) * NTOK];

    for (int n = tid; n < 1024; n += 256)
        bufA[n] = make_float2(kv0[n], kv1[n]);
    __syncthreads();
    block_fft_t<false>(bufA, tw, tid);

    const float2* Fh = &g_Ff[h * 1024];
    for (int k = tid; k <= 512; k += 256) {
        int nk = (1024 - k) & 1023;
        float2 Z = bufA[k];
        float2 Y = bufA[nk];
        float Ar = 0.5f * (Z.x + Y.x), Ai = 0.5f * (Z.y - Y.y);
        float Br = 0.5f * (Z.y + Y.y), Bi = 0.5f * (Y.x - Z.x);
        float2 F = Fh[k];
        float P1r = Ar * F.x - Ai * F.y, P1i = Ar * F.y + Ai * F.x;
        float P2r = Br * F.x - Bi * F.y, P2i = Br * F.y + Bi * F.x;
        bufB[k] = make_float2(P1r - P2i, P1i + P2r);
        if (k != 0 && k != 512)               // self-paired bins: only one write
            bufB[nk] = make_float2(P1r + P2i, -P1i + P2r);
    }
    __syncthreads();
    block_fft_t<true>(bufB, tw, tid);

    const float inv = 1.f / 1024.f;
    for (int n = tid; n < 1024; n += 256) {
        qp0[n] = qp0[n] * bufB[n].x * inv;
        qp1[n] = qp1[n] * bufB[n].y * inv;
    }
}

// ---------------------------------------------------------------------------
// reg_linear + BN partials
// ---------------------------------------------------------------------------
__global__ void __launch_bounds__(256) reglin_kernel(const float* __restrict__ Wm0,
                                                     const float* __restrict__ Wm1)
{
    __shared__ float W0[64 * 64];
    __shared__ float W1[64 * 64];
    __shared__ __align__(16) float hs[8 * 256];
    __shared__ float red0[256], red1[256];
    int tid = threadIdx.x;
    int row0 = blockIdx.x * 8;
    for (int i = tid; i < 4096; i += 256) { W0[i] = Wm0[i]; W1[i] = Wm1[i]; }
    for (int i = tid; i < 2048; i += 256) hs[i] = g_h[(size_t)row0 * DCH + i];
    __syncthreads();
    int k = tid & 63, grp = tid >> 6;
    float ls0 = 0.f, ls1 = 0.f;
    #pragma unroll
    for (int tt = 0; tt < 2; tt++) {
        int t = grp * 2 + tt;
        const float* hr = &hs[t * 256];
        float s = 0.f, v0 = 0.f, v1 = 0.f, v2 = 0.f;
        #pragma unroll 8
        for (int m = 0; m < 64; m++) {
            float4 hv = *(const float4*)&hr[m * 4];
            float w0 = W0[m * 64 + k];
            float w1 = W1[m * 64 + k];
            s  += hv.x * w0;
            v0 += hv.y * w1;
            v1 += hv.z * w1;
            v2 += hv.w * w1;
        }
        *(float4*)&g_y[(size_t)(row0 + t) * DCH + k * 4] = make_float4(s, v0, v1, v2);
        ls0 += s * s;
        ls1 += v0 * v0 + v1 * v1 + v2 * v2;
    }
    red0[tid] = ls0; red1[tid] = ls1;
    __syncthreads();
    if (grp == 0) {
        float t0 = red0[k] + red0[64 + k] + red0[128 + k] + red0[192 + k];
        float t1 = red1[k] + red1[64 + k] + red1[128 + k] + red1[192 + k];
        g_part0[k * NBLK_RL + blockIdx.x] = t0;
        g_part1[k * NBLK_RL + blockIdx.x] = t1;
    }
}

__global__ void scale_red_kernel(const float* __restrict__ g0, const float* __restrict__ g1)
{
    int c = blockIdx.x;          // 0..127
    int ch = c & 63;
    const float* src = (c < 64) ? &g_part0[(size_t)ch * NBLK_RL] : &g_part1[(size_t)ch * NBLK_RL];
    int tid = threadIdx.x;
    float s = 0.f;
    for (int i = tid; i < NBLK_RL; i += 256) s += src[i];
    __shared__ float red[256];
    red[tid] = s;
    __syncthreads();
    for (int st = 128; st; st >>= 1) {
        if (tid < st) red[tid] += red[tid + st];
        __syncthreads();
    }
    if (tid == 0) {
        float norm = sqrtf(red[0] / (float)RTOT + EPSF);
        if (c < 64) g_scale0[ch] = g0[ch] / norm;
        else        g_scale1[ch] = g1[ch] / norm;
    }
}

__global__ void actres_kernel()
{
    size_t idx = (size_t)blockIdx.x * 256 + threadIdx.x;   // over RTOT*64 irreps
    int m = (int)(idx & 63);
    float4 yv = *(float4*)&g_y[idx * 4];
    float s  = yv.x * g_scale0[m];
    float sc = g_scale1[m];
    float v0 = yv.y * sc, v1 = yv.z * sc, v2 = yv.w * sc;
    float sg  = 1.f / (1.f + __expf(-fabsf(s)));
    float vn  = sqrtf(v0 * v0 + v1 * v1 + v2 * v2 + EPSF);
    float sgv = 1.f / (1.f + __expf(-vn));
    float4* hp = (float4*)&g_h[idx * 4];
    float4 hv = *hp;
    hv.x += s * sg;
    hv.y += v0 * sgv;
    hv.z += v1 * sgv;
    hv.w += v2 * sgv;
    *hp = hv;
}

__global__ void pool_kernel(const float* __restrict__ w_out, float* __restrict__ out)
{
    int b = blockIdx.x;
    int tid = threadIdx.x;   // 256
    __shared__ float wsh[64];
    if (tid < 64) wsh[tid] = w_out[tid];
    __syncthreads();
    float a0 = 0.f, a1 = 0.f, a2 = 0.f;
    for (int n = tid; n < NTOK; n += 256) {
        const float* hr = &g_h[((size_t)b * NTOK + n) * DCH];
        #pragma unroll 8
        for (int m = 0; m < 64; m++) {
            float w = wsh[m];
            float4 hv = *(const float4*)&hr[m * 4];
            a0 += hv.y * w;
            a1 += hv.z * w;
            a2 += hv.w * w;
        }
    }
    __shared__ float r0[256], r1[256], r2[256];
    r0[tid] = a0; r1[tid] = a1; r2[tid] = a2;
    __syncthreads();
    for (int st = 128; st; st >>= 1) {
        if (tid < st) { r0[tid] += r0[tid + st]; r1[tid] += r1[tid + st]; r2[tid] += r2[tid + st]; }
        __syncthreads();
    }
    if (tid == 0) {
        out[b * 3 + 0] = r0[0] / (float)NTOK;
        out[b * 3 + 1] = r1[0] / (float)NTOK;
        out[b * 3 + 2] = r2[0] / (float)NTOK;
    }
}

// ---------------------------------------------------------------------------
extern "C" void kernel_launch(void* const* d_in, const int* in_sizes, int n_in,
                              void* d_out, int out_size)
{
    (void)in_sizes; (void)n_in; (void)out_size;
    const float* x       = (const float*)d_in[0];
    const float* tok_emb = (const float*)d_in[1];
    const float* Wf      = (const float*)d_in[2];
    const float* wv      = (const float*)d_in[3];
    const float* w_out   = (const float*)d_in[4];
    const int Hs[3] = {360, 360, 160};

    init_h_kernel<<<NTOK, 256>>>(x, tok_emb, Wf, wv);

    for (int L = 0; L < 3; L++) {
        int base = 5 + L * 9;
        const float* Wq   = (const float*)d_in[base + 0];
        const float* Wk   = (const float*)d_in[base + 1];
        const float* Wvw  = (const float*)d_in[base + 2];
        const float* filt = (const float*)d_in[base + 3];
        const float* Wo   = (const float*)d_in[base + 4];
        const float* Wm0  = (const float*)d_in[base + 5];
        const float* Wm1  = (const float*)d_in[base + 6];
        const float* g0   = (const float*)d_in[base + 7];
        const float* g1   = (const float*)d_in[base + 8];
        int H = Hs[L];

        gemm_qkv<<<dim3((H + 63) / 64, RTOT / 64), 256>>>(Wq, Wk, Wvw, H);
        fft_filt_kernel<<<H, 256>>>(filt, H);
        conv_kernel<<<dim3(H, BSZ / 2), 256>>>(H);
        gemm_out<<<dim3(DCH / 128, RTOT / 128), 256>>>(Wo, H);
        reglin_kernel<<<NBLK_RL, 256>>>(Wm0, Wm1);
        scale_red_kernel<<<128, 256>>>(g0, g1);
        actres_kernel<<<RTOT * 64 / 256, 256>>>();
    }

    pool_kernel<<<BSZ, 256>>>(w_out, (float*)d_out);
}

// round 4
// speedup vs baseline: 1.4640x; 1.1816x over previous
#include <cuda_runtime.h>
#include <math.h>
#include <stdint.h>

// Problem constants
#define BSZ   64
#define NTOK  1024
#define MCH   64
#define DCH   256       // 4*M
#define PDIM  64
#define RTOT  (BSZ*NTOK)   // 65536
#define HMAX  360
#define HPAD  384          // HMAX padded to 64
#define EPSF  1e-5f
#define NBLK_RL (RTOT/8)

// -------- scratch (static __device__ globals) --------
__device__ __align__(16) float g_h[(size_t)RTOT*DCH];
__device__ __align__(16) float g_y[(size_t)RTOT*DCH];
__device__ __align__(16) float g_q[(size_t)BSZ*HMAX*NTOK];
__device__ __align__(16) float g_kv[(size_t)BSZ*HMAX*NTOK];
__device__ __align__(16) float2 g_Ff[HMAX*NTOK];
__device__ __align__(16) float2 g_Wsp[3][DCH][HPAD];     // qkv weights (hi,lo)
__device__ __align__(16) float2 g_Wosp[HPAD][DCH];       // Wo (hi,lo)
__device__ float g_part0[MCH*NBLK_RL];
__device__ float g_part1[MCH*NBLK_RL];
__device__ float g_scale0[MCH];
__device__ float g_scale1[MCH];

// ---------------------------------------------------------------------------
__device__ __forceinline__ void mma_tf32(float* c, const uint32_t* a, const uint32_t* b)
{
    asm volatile(
        "mma.sync.aligned.m16n8k8.row.col.f32.tf32.tf32.f32 "
        "{%0,%1,%2,%3}, {%4,%5,%6,%7}, {%8,%9}, {%0,%1,%2,%3};\n"
        : "+f"(c[0]), "+f"(c[1]), "+f"(c[2]), "+f"(c[3])
        : "r"(a[0]), "r"(a[1]), "r"(a[2]), "r"(a[3]), "r"(b[0]), "r"(b[1]));
}

__device__ __forceinline__ float tf32_rna_f(float x)
{
    uint32_t r;
    asm("cvt.rna.tf32.f32 %0, %1;" : "=r"(r) : "f"(x));
    return __uint_as_float(r);
}

__device__ __forceinline__ float2 cmul(float2 a, float2 b)
{
    return make_float2(a.x*b.x - a.y*b.y, a.x*b.y + a.y*b.x);
}
__device__ __forceinline__ float2 cadd(float2 a, float2 b){ return make_float2(a.x+b.x, a.y+b.y); }
__device__ __forceinline__ float2 csub(float2 a, float2 b){ return make_float2(a.x-b.x, a.y-b.y); }

// ---------------------------------------------------------------------------
// init h
// ---------------------------------------------------------------------------
__global__ void init_h_kernel(const float* __restrict__ x,
                              const float* __restrict__ tok_emb,
                              const float* __restrict__ Wf,
                              const float* __restrict__ wv)
{
    int n = blockIdx.x;
    int tid = threadIdx.x;   // 256
    __shared__ float f[PDIM];
    __shared__ float s0[MCH];
    if (tid < PDIM) {
        int p = tid;
        int j2 = p & ~1;
        float div = expf(-logf(10000.0f) * (float)j2 / (float)PDIM);
        float ang = (float)n * div;
        float pe = (p & 1) ? cosf(ang) : sinf(ang);
        int tt = (n == NTOK - 1) ? 2 : (n & 1);
        f[p] = pe + tok_emb[tt * PDIM + p];
    }
    __syncthreads();
    if (tid < MCH) {
        float acc = 0.f;
        #pragma unroll 8
        for (int p = 0; p < PDIM; p++) acc += f[p] * Wf[p * MCH + tid];
        s0[tid] = acc;
    }
    __syncthreads();
    int m = tid >> 2, r = tid & 3;
    float wvm = wv[m];
    float sv = s0[m];
    for (int b = 0; b < BSZ; b++) {
        float val;
        if (r == 0) val = sv;
        else        val = x[((size_t)b * NTOK + n) * 3 + (r - 1)] * wvm;
        g_h[((size_t)b * NTOK + n) * DCH + tid] = val;
    }
}

// ---------------------------------------------------------------------------
// weight pre-split (hi = rna-tf32, lo = w - hi) into padded buffers
// ---------------------------------------------------------------------------
__global__ void presplit_qkv(const float* __restrict__ Wq,
                             const float* __restrict__ Wk,
                             const float* __restrict__ Wv2, int H)
{
    int idx = blockIdx.x * 256 + threadIdx.x;   // over 256*384
    int k = idx / HPAD, h = idx % HPAD;
    const float* Ws[3] = {Wq, Wk, Wv2};
    #pragma unroll
    for (int m = 0; m < 3; m++) {
        float w = (h < H) ? Ws[m][(size_t)k * H + h] : 0.f;
        float hi = tf32_rna_f(w);
        g_Wsp[m][k][h] = make_float2(hi, w - hi);
    }
}

__global__ void presplit_wo(const float* __restrict__ Wo, int H)
{
    int idx = blockIdx.x * 256 + threadIdx.x;   // over 384*256
    int k = idx >> 8, n = idx & 255;
    float w = (k < H) ? Wo[(size_t)k * DCH + n] : 0.f;
    float hi = tf32_rna_f(w);
    g_Wosp[k][n] = make_float2(hi, w - hi);
}

// ---------------------------------------------------------------------------
// Fused q/k/v GEMM, 2-term tf32. Tile 64x64, kstep 16, 256 thr.
// ---------------------------------------------------------------------------
__global__ void __launch_bounds__(256) gemm_qkv(int H)
{
    int row0 = blockIdx.y * 64;
    int col0 = blockIdx.x * 64;
    int b = row0 >> 10;
    int nbase = row0 & (NTOK - 1);

    __shared__ __align__(16) float  As[64][20];    // rounded A [row][k]
    __shared__ __align__(16) float2 Bq[16][66];    // (hi,lo) [k][n]
    __shared__ __align__(16) float2 Bk[16][66];
    __shared__ __align__(16) float2 Bv[16][66];

    int tid = threadIdx.x;
    int wid = tid >> 5, lane = tid & 31;
    int g = lane >> 2, t = lane & 3;
    int wr = wid >> 2, wc = wid & 3;

    float accq[2][2][4] = {}, acck[2][2][4] = {}, accv[2][2][4] = {};

    int arow = tid >> 2, akq = tid & 3;

    for (int k0 = 0; k0 < DCH; k0 += 16) {
        // A: 64x16 = 256 float4, 1/thread, rounded
        {
            float4 a4 = *(const float4*)&g_h[(size_t)(row0 + arow) * DCH + k0 + akq * 4];
            a4.x = tf32_rna_f(a4.x); a4.y = tf32_rna_f(a4.y);
            a4.z = tf32_rna_f(a4.z); a4.w = tf32_rna_f(a4.w);
            *(float4*)&As[arow][akq * 4] = a4;
        }
        // B: per matrix 16x64 float2 = 512 float4, 2/thread
        #pragma unroll
        for (int i = 0; i < 2; i++) {
            int idx = tid + i * 256;
            int kr = idx >> 5, hq = idx & 31;
            *(float4*)&Bq[kr][hq * 2] = *(const float4*)&g_Wsp[0][k0 + kr][col0 + hq * 2];
            *(float4*)&Bk[kr][hq * 2] = *(const float4*)&g_Wsp[1][k0 + kr][col0 + hq * 2];
            *(float4*)&Bv[kr][hq * 2] = *(const float4*)&g_Wsp[2][k0 + kr][col0 + hq * 2];
        }
        __syncthreads();
        #pragma unroll
        for (int ks = 0; ks < 2; ks++) {
            int kb = ks * 8;
            uint32_t ah[2][4];
            #pragma unroll
            for (int mf = 0; mf < 2; mf++) {
                int rb = wr * 32 + mf * 16;
                ah[mf][0] = __float_as_uint(As[rb + g     ][kb + t    ]);
                ah[mf][1] = __float_as_uint(As[rb + g + 8 ][kb + t    ]);
                ah[mf][2] = __float_as_uint(As[rb + g     ][kb + t + 4]);
                ah[mf][3] = __float_as_uint(As[rb + g + 8 ][kb + t + 4]);
            }
            #pragma unroll
            for (int nf = 0; nf < 2; nf++) {
                int nb = wc * 16 + nf * 8 + g;
                float2 p0, p1;
                uint32_t bh[2], bl[2];
                // Q
                p0 = Bq[kb + t][nb]; p1 = Bq[kb + t + 4][nb];
                bh[0] = __float_as_uint(p0.x); bl[0] = __float_as_uint(p0.y);
                bh[1] = __float_as_uint(p1.x); bl[1] = __float_as_uint(p1.y);
                #pragma unroll
                for (int mf = 0; mf < 2; mf++) {
                    mma_tf32(accq[mf][nf], ah[mf], bh);
                    mma_tf32(accq[mf][nf], ah[mf], bl);
                }
                // K
                p0 = Bk[kb + t][nb]; p1 = Bk[kb + t + 4][nb];
                bh[0] = __float_as_uint(p0.x); bl[0] = __float_as_uint(p0.y);
                bh[1] = __float_as_uint(p1.x); bl[1] = __float_as_uint(p1.y);
                #pragma unroll
                for (int mf = 0; mf < 2; mf++) {
                    mma_tf32(acck[mf][nf], ah[mf], bh);
                    mma_tf32(acck[mf][nf], ah[mf], bl);
                }
                // V
                p0 = Bv[kb + t][nb]; p1 = Bv[kb + t + 4][nb];
                bh[0] = __float_as_uint(p0.x); bl[0] = __float_as_uint(p0.y);
                bh[1] = __float_as_uint(p1.x); bl[1] = __float_as_uint(p1.y);
                #pragma unroll
                for (int mf = 0; mf < 2; mf++) {
                    mma_tf32(accv[mf][nf], ah[mf], bh);
                    mma_tf32(accv[mf][nf], ah[mf], bl);
                }
            }
        }
        __syncthreads();
    }
    // epilogue: q and k*v to [B,H,N]
    #pragma unroll
    for (int mf = 0; mf < 2; mf++) {
        #pragma unroll
        for (int nf = 0; nf < 2; nf++) {
            #pragma unroll
            for (int cc = 0; cc < 2; cc++) {
                int col = col0 + wc * 16 + nf * 8 + t * 2 + cc;
                if (col < H) {
                    size_t base = ((size_t)b * H + col) * NTOK + nbase + wr * 32 + mf * 16 + g;
                    g_q[base]     = accq[mf][nf][cc];
                    g_q[base + 8] = accq[mf][nf][cc + 2];
                    g_kv[base]     = acck[mf][nf][cc]     * accv[mf][nf][cc];
                    g_kv[base + 8] = acck[mf][nf][cc + 2] * accv[mf][nf][cc + 2];
                }
            }
        }
    }
}

// ---------------------------------------------------------------------------
// Wo GEMM + residual, 2-term tf32. Tile 128x128, kstep 16.
// ---------------------------------------------------------------------------
__global__ void __launch_bounds__(256) gemm_out(int H)
{
    int row0 = blockIdx.y * 128;
    int col0 = blockIdx.x * 128;
    int b = row0 >> 10;
    int nbase = row0 & (NTOK - 1);

    __shared__ __align__(16) float  As[16][136];   // rounded A [k][row]
    __shared__ __align__(16) float2 Bs[16][130];   // (hi,lo) [k][n]

    int tid = threadIdx.x;
    int wid = tid >> 5, lane = tid & 31;
    int g = lane >> 2, t = lane & 3;
    int wr = wid >> 2, wc = wid & 3;

    float acc[4][4][4] = {};

    int ksteps = (H + 15) >> 4;
    for (int ki = 0; ki < ksteps; ki++) {
        int k0 = ki * 16;
        // A: 16 k x 128 rows = 512 float4, 2/thread, rounded + guard
        #pragma unroll
        for (int i = 0; i < 2; i++) {
            int idx = tid + i * 256;
            int k = idx >> 5, mq = idx & 31;
            float4 v = make_float4(0.f,0.f,0.f,0.f);
            if (k0 + k < H) {
                v = *(const float4*)&g_q[((size_t)b * H + k0 + k) * NTOK + nbase + mq * 4];
                v.x = tf32_rna_f(v.x); v.y = tf32_rna_f(v.y);
                v.z = tf32_rna_f(v.z); v.w = tf32_rna_f(v.w);
            }
            *(float4*)&As[k][mq * 4] = v;
        }
        // B: 16 x 128 float2 = 1024 float4, 4/thread (padded storage)
        #pragma unroll
        for (int i = 0; i < 4; i++) {
            int idx = tid + i * 256;
            int k = idx >> 6, nq = idx & 63;
            *(float4*)&Bs[k][nq * 2] = *(const float4*)&g_Wosp[k0 + k][col0 + nq * 2];
        }
        __syncthreads();
        #pragma unroll
        for (int ks = 0; ks < 2; ks++) {
            int kb = ks * 8;
            uint32_t ah[4][4];
            #pragma unroll
            for (int mf = 0; mf < 4; mf++) {
                int rb = wr * 64 + mf * 16;
                ah[mf][0] = __float_as_uint(As[kb + t    ][rb + g    ]);
                ah[mf][1] = __float_as_uint(As[kb + t    ][rb + g + 8]);
                ah[mf][2] = __float_as_uint(As[kb + t + 4][rb + g    ]);
                ah[mf][3] = __float_as_uint(As[kb + t + 4][rb + g + 8]);
            }
            #pragma unroll
            for (int nf = 0; nf < 4; nf++) {
                int nb = wc * 32 + nf * 8 + g;
                float2 p0 = Bs[kb + t][nb];
                float2 p1 = Bs[kb + t + 4][nb];
                uint32_t bh[2] = {__float_as_uint(p0.x), __float_as_uint(p1.x)};
                uint32_t bl[2] = {__float_as_uint(p0.y), __float_as_uint(p1.y)};
                #pragma unroll
                for (int mf = 0; mf < 4; mf++) {
                    mma_tf32(acc[mf][nf], ah[mf], bh);
                    mma_tf32(acc[mf][nf], ah[mf], bl);
                }
            }
        }
        __syncthreads();
    }
    #pragma unroll
    for (int mf = 0; mf < 4; mf++) {
        #pragma unroll
        for (int nf = 0; nf < 4; nf++) {
            int col = col0 + wc * 32 + nf * 8 + t * 2;
            #pragma unroll
            for (int rr = 0; rr < 2; rr++) {
                int row = row0 + wr * 64 + mf * 16 + g + rr * 8;
                float2* hp = (float2*)&g_h[(size_t)row * DCH + col];
                float2 hv = *hp;
                hv.x += acc[mf][nf][rr * 2];
                hv.y += acc[mf][nf][rr * 2 + 1];
                *hp = hv;
            }
        }
    }
}

// ---------------------------------------------------------------------------
// 1024-pt radix-4 Stockham FFT (DIF), natural order in & out.
// 256 threads, 5 stages, ping-pong x->y. Result lands in y.
// tw[k] = exp(-2*pi*i*k/1024), k < 256.
// ---------------------------------------------------------------------------
template<bool INV>
__device__ __forceinline__ void fft1024(float2* x, float2* y, const float2* tw, int tid)
{
    float2* src = x;
    float2* dst = y;
    #pragma unroll
    for (int s = 0; s < 5; s++) {
        int m = 1 << (2 * s);
        float2 c0 = src[tid];
        float2 c1 = src[tid + 256];
        float2 c2 = src[tid + 512];
        float2 c3 = src[tid + 768];
        float2 t0 = cadd(c0, c2);
        float2 t1 = csub(c0, c2);
        float2 t2 = cadd(c1, c3);
        float2 d  = csub(c1, c3);
        float2 t3 = INV ? make_float2(-d.y, d.x) : make_float2(d.y, -d.x);
        int jm = tid & ~(m - 1);
        float2 w1 = tw[jm];
        if (INV) w1.y = -w1.y;
        float2 w2 = cmul(w1, w1);
        float2 w3 = cmul(w2, w1);
        int base = tid + 3 * jm;
        dst[base]         = cadd(t0, t2);
        dst[base + m]     = cmul(w1, cadd(t1, t3));
        dst[base + 2 * m] = cmul(w2, csub(t0, t2));
        dst[base + 3 * m] = cmul(w3, csub(t1, t3));
        __syncthreads();
        float2* tmp = src; src = dst; dst = tmp;
    }
}

__global__ void fft_filt_kernel(const float* __restrict__ filt, int H)
{
    int h = blockIdx.x;
    int tid = threadIdx.x;
    __shared__ float2 bufA[1024];
    __shared__ float2 bufB[1024];
    __shared__ float2 tw[256];
    {
        float ang = -6.283185307179586f * (float)tid / 1024.f;
        float sn, cs;
        sincosf(ang, &sn, &cs);
        tw[tid] = make_float2(cs, sn);
    }
    for (int n = tid; n < 1024; n += 256)
        bufA[n] = make_float2(filt[(size_t)n * H + h], 0.f);
    __syncthreads();
    fft1024<false>(bufA, bufB, tw, tid);
    for (int f = tid; f < 1024; f += 256)
        g_Ff[h * 1024 + f] = bufB[f];
}

// Packed-pair conv: two batch rows per block share fwd + inv FFT.
__global__ void conv_kernel(int H)
{
    int h = blockIdx.x;
    int b0 = blockIdx.y * 2, b1 = b0 + 1;
    int tid = threadIdx.x;
    __shared__ float2 bufA[1024];
    __shared__ float2 bufB[1024];
    __shared__ float2 tw[256];
    {
        float ang = -6.283185307179586f * (float)tid / 1024.f;
        float sn, cs;
        sincosf(ang, &sn, &cs);
        tw[tid] = make_float2(cs, sn);
    }

    const float* kv0 = &g_kv[((size_t)b0 * H + h) * NTOK];
    const float* kv1 = &g_kv[((size_t)b1 * H + h) * NTOK];
    float* qp0 = &g_q[((size_t)b0 * H + h) * NTOK];
    float* qp1 = &g_q[((size_t)b1 * H + h) * NTOK];

    {
        float4 u = *(const float4*)&kv0[tid * 4];
        float4 v = *(const float4*)&kv1[tid * 4];
        bufA[tid * 4 + 0] = make_float2(u.x, v.x);
        bufA[tid * 4 + 1] = make_float2(u.y, v.y);
        bufA[tid * 4 + 2] = make_float2(u.z, v.z);
        bufA[tid * 4 + 3] = make_float2(u.w, v.w);
    }
    __syncthreads();
    fft1024<false>(bufA, bufB, tw, tid);    // result in bufB

    // spectral combine: bufB -> bufA
    const float2* Fh = &g_Ff[h * 1024];
    for (int k = tid; k <= 512; k += 256) {
        int nk = (1024 - k) & 1023;
        float2 Z = bufB[k];
        float2 Y = bufB[nk];
        float Ar = 0.5f * (Z.x + Y.x), Ai = 0.5f * (Z.y - Y.y);
        float Br = 0.5f * (Z.y + Y.y), Bi = 0.5f * (Y.x - Z.x);
        float2 F = Fh[k];
        float P1r = Ar * F.x - Ai * F.y, P1i = Ar * F.y + Ai * F.x;
        float P2r = Br * F.x - Bi * F.y, P2i = Br * F.y + Bi * F.x;
        bufA[k] = make_float2(P1r - P2i, P1i + P2r);
        if (k != 0 && k != 512)
            bufA[nk] = make_float2(P1r + P2i, -P1i + P2r);
    }
    __syncthreads();
    fft1024<true>(bufA, bufB, tw, tid);     // result in bufB

    const float inv = 1.f / 1024.f;
    {
        float4 q0 = *(const float4*)&qp0[tid * 4];
        float4 q1 = *(const float4*)&qp1[tid * 4];
        float2 c0 = bufB[tid * 4 + 0];
        float2 c1 = bufB[tid * 4 + 1];
        float2 c2 = bufB[tid * 4 + 2];
        float2 c3 = bufB[tid * 4 + 3];
        q0.x *= c0.x * inv; q0.y *= c1.x * inv; q0.z *= c2.x * inv; q0.w *= c3.x * inv;
        q1.x *= c0.y * inv; q1.y *= c1.y * inv; q1.z *= c2.y * inv; q1.w *= c3.y * inv;
        *(float4*)&qp0[tid * 4] = q0;
        *(float4*)&qp1[tid * 4] = q1;
    }
}

// ---------------------------------------------------------------------------
// reg_linear + BN partials
// ---------------------------------------------------------------------------
__global__ void __launch_bounds__(256) reglin_kernel(const float* __restrict__ Wm0,
                                                     const float* __restrict__ Wm1)
{
    __shared__ float W0[64 * 64];
    __shared__ float W1[64 * 64];
    __shared__ __align__(16) float hs[8 * 256];
    __shared__ float red0[256], red1[256];
    int tid = threadIdx.x;
    int row0 = blockIdx.x * 8;
    for (int i = tid; i < 4096; i += 256) { W0[i] = Wm0[i]; W1[i] = Wm1[i]; }
    for (int i = tid; i < 2048; i += 256) hs[i] = g_h[(size_t)row0 * DCH + i];
    __syncthreads();
    int k = tid & 63, grp = tid >> 6;
    float ls0 = 0.f, ls1 = 0.f;
    #pragma unroll
    for (int tt = 0; tt < 2; tt++) {
        int t = grp * 2 + tt;
        const float* hr = &hs[t * 256];
        float s = 0.f, v0 = 0.f, v1 = 0.f, v2 = 0.f;
        #pragma unroll 8
        for (int m = 0; m < 64; m++) {
            float4 hv = *(const float4*)&hr[m * 4];
            float w0 = W0[m * 64 + k];
            float w1 = W1[m * 64 + k];
            s  += hv.x * w0;
            v0 += hv.y * w1;
            v1 += hv.z * w1;
            v2 += hv.w * w1;
        }
        *(float4*)&g_y[(size_t)(row0 + t) * DCH + k * 4] = make_float4(s, v0, v1, v2);
        ls0 += s * s;
        ls1 += v0 * v0 + v1 * v1 + v2 * v2;
    }
    red0[tid] = ls0; red1[tid] = ls1;
    __syncthreads();
    if (grp == 0) {
        float t0 = red0[k] + red0[64 + k] + red0[128 + k] + red0[192 + k];
        float t1 = red1[k] + red1[64 + k] + red1[128 + k] + red1[192 + k];
        g_part0[k * NBLK_RL + blockIdx.x] = t0;
        g_part1[k * NBLK_RL + blockIdx.x] = t1;
    }
}

__global__ void scale_red_kernel(const float* __restrict__ g0, const float* __restrict__ g1)
{
    int c = blockIdx.x;          // 0..127
    int ch = c & 63;
    const float* src = (c < 64) ? &g_part0[(size_t)ch * NBLK_RL] : &g_part1[(size_t)ch * NBLK_RL];
    int tid = threadIdx.x;
    float s = 0.f;
    for (int i = tid; i < NBLK_RL; i += 256) s += src[i];
    __shared__ float red[256];
    red[tid] = s;
    __syncthreads();
    for (int st = 128; st; st >>= 1) {
        if (tid < st) red[tid] += red[tid + st];
        __syncthreads();
    }
    if (tid == 0) {
        float norm = sqrtf(red[0] / (float)RTOT + EPSF);
        if (c < 64) g_scale0[ch] = g0[ch] / norm;
        else        g_scale1[ch] = g1[ch] / norm;
    }
}

__global__ void actres_kernel()
{
    size_t idx = (size_t)blockIdx.x * 256 + threadIdx.x;
    int m = (int)(idx & 63);
    float4 yv = *(float4*)&g_y[idx * 4];
    float s  = yv.x * g_scale0[m];
    float sc = g_scale1[m];
    float v0 = yv.y * sc, v1 = yv.z * sc, v2 = yv.w * sc;
    float sg  = 1.f / (1.f + __expf(-fabsf(s)));
    float vn  = sqrtf(v0 * v0 + v1 * v1 + v2 * v2 + EPSF);
    float sgv = 1.f / (1.f + __expf(-vn));
    float4* hp = (float4*)&g_h[idx * 4];
    float4 hv = *hp;
    hv.x += s * sg;
    hv.y += v0 * sgv;
    hv.z += v1 * sgv;
    hv.w += v2 * sgv;
    *hp = hv;
}

__global__ void pool_kernel(const float* __restrict__ w_out, float* __restrict__ out)
{
    int b = blockIdx.x;
    int tid = threadIdx.x;
    __shared__ float wsh[64];
    if (tid < 64) wsh[tid] = w_out[tid];
    __syncthreads();
    float a0 = 0.f, a1 = 0.f, a2 = 0.f;
    for (int n = tid; n < NTOK; n += 256) {
        const float* hr = &g_h[((size_t)b * NTOK + n) * DCH];
        #pragma unroll 8
        for (int m = 0; m < 64; m++) {
            float w = wsh[m];
            float4 hv = *(const float4*)&hr[m * 4];
            a0 += hv.y * w;
            a1 += hv.z * w;
            a2 += hv.w * w;
        }
    }
    __shared__ float r0[256], r1[256], r2[256];
    r0[tid] = a0; r1[tid] = a1; r2[tid] = a2;
    __syncthreads();
    for (int st = 128; st; st >>= 1) {
        if (tid < st) { r0[tid] += r0[tid + st]; r1[tid] += r1[tid + st]; r2[tid] += r2[tid + st]; }
        __syncthreads();
    }
    if (tid == 0) {
        out[b * 3 + 0] = r0[0] / (float)NTOK;
        out[b * 3 + 1] = r1[0] / (float)NTOK;
        out[b * 3 + 2] = r2[0] / (float)NTOK;
    }
}

// ---------------------------------------------------------------------------
extern "C" void kernel_launch(void* const* d_in, const int* in_sizes, int n_in,
                              void* d_out, int out_size)
{
    (void)in_sizes; (void)n_in; (void)out_size;
    const float* x       = (const float*)d_in[0];
    const float* tok_emb = (const float*)d_in[1];
    const float* Wf      = (const float*)d_in[2];
    const float* wv      = (const float*)d_in[3];
    const float* w_out   = (const float*)d_in[4];
    const int Hs[3] = {360, 360, 160};

    init_h_kernel<<<NTOK, 256>>>(x, tok_emb, Wf, wv);

    for (int L = 0; L < 3; L++) {
        int base = 5 + L * 9;
        const float* Wq   = (const float*)d_in[base + 0];
        const float* Wk   = (const float*)d_in[base + 1];
        const float* Wvw  = (const float*)d_in[base + 2];
        const float* filt = (const float*)d_in[base + 3];
        const float* Wo   = (const float*)d_in[base + 4];
        const float* Wm0  = (const float*)d_in[base + 5];
        const float* Wm1  = (const float*)d_in[base + 6];
        const float* g0   = (const float*)d_in[base + 7];
        const float* g1   = (const float*)d_in[base + 8];
        int H = Hs[L];

        presplit_qkv<<<DCH * HPAD / 256, 256>>>(Wq, Wk, Wvw, H);
        presplit_wo<<<HPAD * DCH / 256, 256>>>(Wo, H);
        gemm_qkv<<<dim3((H + 63) / 64, RTOT / 64), 256>>>(H);
        fft_filt_kernel<<<H, 256>>>(filt, H);
        conv_kernel<<<dim3(H, BSZ / 2), 256>>>(H);
        gemm_out<<<dim3(DCH / 128, RTOT / 128), 256>>>(H);
        reglin_kernel<<<NBLK_RL, 256>>>(Wm0, Wm1);
        scale_red_kernel<<<128, 256>>>(g0, g1);
        actres_kernel<<<RTOT * 64 / 256, 256>>>();
    }

    pool_kernel<<<BSZ, 256>>>(w_out, (float*)d_out);
}

// round 5
// speedup vs baseline: 1.9139x; 1.3073x over previous
#include <cuda_runtime.h>
#include <math.h>
#include <stdint.h>

// Problem constants
#define BSZ   64
#define NTOK  1024
#define MCH   64
#define DCH   256       // 4*M
#define PDIM  64
#define RTOT  (BSZ*NTOK)   // 65536
#define HMAX  360
#define HPAD  384
#define EPSF  1e-5f
#define NBLK2 (RTOT/32)    // 2048 reglin blocks

// -------- scratch (static __device__ globals) --------
__device__ __align__(16) float g_h[(size_t)RTOT*DCH];
__device__ __align__(16) float g_y[(size_t)RTOT*DCH];
__device__ __align__(16) float g_q[(size_t)BSZ*HMAX*NTOK];
__device__ __align__(16) float g_kv[(size_t)BSZ*HMAX*NTOK];
__device__ __align__(16) float2 g_Ff[HMAX*NTOK];
// fragment-packed weights: [mat][kb][cb][lane][4] ; (b0h,b0l,b1h,b1l)
__device__ __align__(16) float g_WspF[3][32][HPAD/8][32][4];
__device__ __align__(16) float g_WoF[HPAD/8][32][32][4];
__device__ float g_part0[MCH*NBLK2];
__device__ float g_part1[MCH*NBLK2];
__device__ float g_scale0[MCH];
__device__ float g_scale1[MCH];

// ---------------------------------------------------------------------------
__device__ __forceinline__ void mma_tf32(float* c, const uint32_t* a, const uint32_t* b)
{
    asm volatile(
        "mma.sync.aligned.m16n8k8.row.col.f32.tf32.tf32.f32 "
        "{%0,%1,%2,%3}, {%4,%5,%6,%7}, {%8,%9}, {%0,%1,%2,%3};\n"
        : "+f"(c[0]), "+f"(c[1]), "+f"(c[2]), "+f"(c[3])
        : "r"(a[0]), "r"(a[1]), "r"(a[2]), "r"(a[3]), "r"(b[0]), "r"(b[1]));
}

__device__ __forceinline__ float tf32_rna_f(float x)
{
    uint32_t r;
    asm("cvt.rna.tf32.f32 %0, %1;" : "=r"(r) : "f"(x));
    return __uint_as_float(r);
}
__device__ __forceinline__ uint32_t rna_bits(float x)
{
    uint32_t r;
    asm("cvt.rna.tf32.f32 %0, %1;" : "=r"(r) : "f"(x));
    return r;
}

__device__ __forceinline__ uint32_t sAddr(const void* p)
{
    return (uint32_t)__cvta_generic_to_shared(p);
}
__device__ __forceinline__ void cp16(uint32_t dst, const void* src)
{
    asm volatile("cp.async.cg.shared.global [%0], [%1], 16;\n" :: "r"(dst), "l"(src));
}
#define CP_COMMIT() asm volatile("cp.async.commit_group;\n")
#define CP_WAIT1()  asm volatile("cp.async.wait_group 1;\n")
#define CP_WAIT0()  asm volatile("cp.async.wait_group 0;\n")

__device__ __forceinline__ float2 cmul(float2 a, float2 b)
{ return make_float2(a.x*b.x - a.y*b.y, a.x*b.y + a.y*b.x); }
__device__ __forceinline__ float2 cadd(float2 a, float2 b){ return make_float2(a.x+b.x, a.y+b.y); }
__device__ __forceinline__ float2 csub(float2 a, float2 b){ return make_float2(a.x-b.x, a.y-b.y); }

// ---------------------------------------------------------------------------
// init h
// ---------------------------------------------------------------------------
__global__ void init_h_kernel(const float* __restrict__ x,
                              const float* __restrict__ tok_emb,
                              const float* __restrict__ Wf,
                              const float* __restrict__ wv)
{
    int n = blockIdx.x;
    int tid = threadIdx.x;   // 256
    __shared__ float f[PDIM];
    __shared__ float s0[MCH];
    if (tid < PDIM) {
        int p = tid;
        int j2 = p & ~1;
        float div = expf(-logf(10000.0f) * (float)j2 / (float)PDIM);
        float ang = (float)n * div;
        float pe = (p & 1) ? cosf(ang) : sinf(ang);
        int tt = (n == NTOK - 1) ? 2 : (n & 1);
        f[p] = pe + tok_emb[tt * PDIM + p];
    }
    __syncthreads();
    if (tid < MCH) {
        float acc = 0.f;
        #pragma unroll 8
        for (int p = 0; p < PDIM; p++) acc += f[p] * Wf[p * MCH + tid];
        s0[tid] = acc;
    }
    __syncthreads();
    int m = tid >> 2, r = tid & 3;
    float wvm = wv[m];
    float sv = s0[m];
    for (int b = 0; b < BSZ; b++) {
        float val;
        if (r == 0) val = sv;
        else        val = x[((size_t)b * NTOK + n) * 3 + (r - 1)] * wvm;
        g_h[((size_t)b * NTOK + n) * DCH + tid] = val;
    }
}

// ---------------------------------------------------------------------------
// weight pre-split into fragment-packed layout
// ---------------------------------------------------------------------------
__global__ void presplit_qkv(const float* __restrict__ Wq,
                             const float* __restrict__ Wk,
                             const float* __restrict__ Wv2, int H)
{
    int idx = blockIdx.x * 256 + threadIdx.x;   // over 256*HPAD
    int k = idx / HPAD, h = idx % HPAD;
    int kb = k >> 3, kk = k & 7;
    int t = kk & 3, pos = kk >> 2;
    int cb = h >> 3, lane = (h & 7) * 4 + t;
    const float* Ws[3] = {Wq, Wk, Wv2};
    #pragma unroll
    for (int m = 0; m < 3; m++) {
        float w = (h < H) ? Ws[m][(size_t)k * H + h] : 0.f;
        float hi = tf32_rna_f(w);
        g_WspF[m][kb][cb][lane][pos * 2]     = hi;
        g_WspF[m][kb][cb][lane][pos * 2 + 1] = w - hi;
    }
}

__global__ void presplit_wo(const float* __restrict__ Wo, int H)
{
    int idx = blockIdx.x * 256 + threadIdx.x;   // over HPAD*256
    int k = idx >> 8, n = idx & 255;
    int kb = k >> 3, kk = k & 7;
    int t = kk & 3, pos = kk >> 2;
    int cb = n >> 3, lane = (n & 7) * 4 + t;
    float w = (k < H) ? Wo[(size_t)k * DCH + n] : 0.f;
    float hi = tf32_rna_f(w);
    g_WoF[kb][cb][lane][pos * 2]     = hi;
    g_WoF[kb][cb][lane][pos * 2 + 1] = w - hi;
}

// ---------------------------------------------------------------------------
// Fused q/k/v GEMM. Tile 128x64, kstep 8, cp.async double buffered.
// Warps 2(m) x 4(n): warp tile 64x16, mf=4, nf=2, 3 mats, 2 tf32 terms.
// ---------------------------------------------------------------------------
__global__ void __launch_bounds__(256, 1) gemm_qkv(int H)
{
    __shared__ __align__(16) float shA[2][128 * 12];
    __shared__ __align__(16) float shB[2][3 * 8 * 128];

    int tid = threadIdx.x;
    int row0 = blockIdx.y * 128;
    int col0 = blockIdx.x * 64;
    int b = row0 >> 10;
    int nbase = row0 & (NTOK - 1);
    int cb0 = col0 >> 3;

    int wid = tid >> 5, lane = tid & 31;
    int g = lane >> 2, t = lane & 3;
    int wr = wid >> 2, wc = wid & 3;

    float accq[4][2][4] = {}, acck[4][2][4] = {}, accv[4][2][4] = {};

    // loaders
    int ar = tid >> 1, ahalf = tid & 1;
    const float* aSrc = &g_h[(size_t)(row0 + ar) * DCH + ahalf * 4];
    uint32_t aDst0 = sAddr(&shA[0][ar * 12 + ahalf * 4]);
    uint32_t aDst1 = sAddr(&shA[1][ar * 12 + ahalf * 4]);

    int bmat = tid >> 8;  (void)bmat;
    // B chunks: c = i*256+tid -> mat, cb, ln
    #define QKV_LOAD(kb, buf)                                                     \
    {                                                                             \
        cp16((buf) ? aDst1 : aDst0, aSrc + (kb) * 8);                             \
        _Pragma("unroll")                                                         \
        for (int i = 0; i < 3; i++) {                                             \
            int c = i * 256 + tid;                                                \
            int mat = c >> 8, rem = c & 255;                                      \
            int cb = rem >> 5, ln = rem & 31;                                     \
            cp16(sAddr(&shB[buf][(mat * 8 + cb) * 128 + ln * 4]),                 \
                 &g_WspF[mat][kb][cb0 + cb][ln][0]);                              \
        }                                                                         \
        CP_COMMIT();                                                              \
    }

    QKV_LOAD(0, 0);

    for (int kb = 0; kb < 32; kb++) {
        if (kb + 1 < 32) { QKV_LOAD(kb + 1, (kb + 1) & 1); CP_WAIT1(); }
        else             { CP_WAIT0(); }
        __syncthreads();
        const float* A = shA[kb & 1];
        const float* B = shB[kb & 1];

        uint32_t ah[4][4];
        #pragma unroll
        for (int mf = 0; mf < 4; mf++) {
            int rb = wr * 64 + mf * 16;
            ah[mf][0] = rna_bits(A[(rb + g)     * 12 + t]);
            ah[mf][1] = rna_bits(A[(rb + g + 8) * 12 + t]);
            ah[mf][2] = rna_bits(A[(rb + g)     * 12 + t + 4]);
            ah[mf][3] = rna_bits(A[(rb + g + 8) * 12 + t + 4]);
        }
        #pragma unroll
        for (int nf = 0; nf < 2; nf++) {
            int cb = wc * 2 + nf;
            float4 bq = *(const float4*)&B[(0 * 8 + cb) * 128 + lane * 4];
            float4 bk = *(const float4*)&B[(1 * 8 + cb) * 128 + lane * 4];
            float4 bv = *(const float4*)&B[(2 * 8 + cb) * 128 + lane * 4];
            uint32_t bh[2], bl[2];
            bh[0] = __float_as_uint(bq.x); bh[1] = __float_as_uint(bq.z);
            bl[0] = __float_as_uint(bq.y); bl[1] = __float_as_uint(bq.w);
            #pragma unroll
            for (int mf = 0; mf < 4; mf++) {
                mma_tf32(accq[mf][nf], ah[mf], bh);
                mma_tf32(accq[mf][nf], ah[mf], bl);
            }
            bh[0] = __float_as_uint(bk.x); bh[1] = __float_as_uint(bk.z);
            bl[0] = __float_as_uint(bk.y); bl[1] = __float_as_uint(bk.w);
            #pragma unroll
            for (int mf = 0; mf < 4; mf++) {
                mma_tf32(acck[mf][nf], ah[mf], bh);
                mma_tf32(acck[mf][nf], ah[mf], bl);
            }
            bh[0] = __float_as_uint(bv.x); bh[1] = __float_as_uint(bv.z);
            bl[0] = __float_as_uint(bv.y); bl[1] = __float_as_uint(bv.w);
            #pragma unroll
            for (int mf = 0; mf < 4; mf++) {
                mma_tf32(accv[mf][nf], ah[mf], bh);
                mma_tf32(accv[mf][nf], ah[mf], bl);
            }
        }
        __syncthreads();
    }

    // epilogue: q and k*v to [B,H,N]
    #pragma unroll
    for (int mf = 0; mf < 4; mf++) {
        #pragma unroll
        for (int nf = 0; nf < 2; nf++) {
            #pragma unroll
            for (int cc = 0; cc < 2; cc++) {
                int col = col0 + wc * 16 + nf * 8 + t * 2 + cc;
                if (col < H) {
                    size_t base = ((size_t)b * H + col) * NTOK + nbase + wr * 64 + mf * 16 + g;
                    g_q[base]     = accq[mf][nf][cc];
                    g_q[base + 8] = accq[mf][nf][cc + 2];
                    g_kv[base]     = acck[mf][nf][cc]     * accv[mf][nf][cc];
                    g_kv[base + 8] = acck[mf][nf][cc + 2] * accv[mf][nf][cc + 2];
                }
            }
        }
    }
}

// ---------------------------------------------------------------------------
// Wo GEMM + residual: g_h[R,256] += G[R,H] @ Wo[H,256].
// Tile 128x128, kstep 8, cp.async double buffered. A pre-rounded by conv.
// ---------------------------------------------------------------------------
__global__ void __launch_bounds__(256, 1) gemm_out(int H)
{
    __shared__ __align__(16) float shA[2][8 * 136];
    __shared__ __align__(16) float shB[2][16 * 128];

    int tid = threadIdx.x;
    int row0 = blockIdx.y * 128;
    int col0 = blockIdx.x * 128;
    int b = row0 >> 10;
    int nbase = row0 & (NTOK - 1);
    int cb0 = col0 >> 3;     // 16 cbs per block

    int wid = tid >> 5, lane = tid & 31;
    int g = lane >> 2, t = lane & 3;
    int wr = wid >> 2, wc = wid & 3;

    float acc[4][4][4] = {};

    int akk = tid >> 5, aseg = tid & 31;
    const float* aRow = &g_q[((size_t)b * H + akk) * NTOK + nbase + aseg * 4];
    size_t aStride = (size_t)8 * NTOK;   // per kb advance

    #define OUT_LOAD(kb, buf)                                                    \
    {                                                                            \
        cp16(sAddr(&shA[buf][akk * 136 + aseg * 4]), aRow + (size_t)(kb) * aStride); \
        _Pragma("unroll")                                                        \
        for (int i = 0; i < 2; i++) {                                            \
            int c = i * 256 + tid;                                               \
            int cb = c >> 5, ln = c & 31;                                        \
            cp16(sAddr(&shB[buf][(cb * 32 + ln) * 4]),                           \
                 &g_WoF[kb][cb0 + cb][ln][0]);                                   \
        }                                                                        \
        CP_COMMIT();                                                             \
    }

    int ksteps = H >> 3;   // 45 or 20 (exact)
    OUT_LOAD(0, 0);

    for (int kb = 0; kb < ksteps; kb++) {
        if (kb + 1 < ksteps) { OUT_LOAD(kb + 1, (kb + 1) & 1); CP_WAIT1(); }
        else                 { CP_WAIT0(); }
        __syncthreads();
        const float* A = shA[kb & 1];
        const float* B = shB[kb & 1];

        uint32_t ah[4][4];
        #pragma unroll
        for (int mf = 0; mf < 4; mf++) {
            int rb = wr * 64 + mf * 16;
            ah[mf][0] = __float_as_uint(A[t       * 136 + rb + g]);
            ah[mf][1] = __float_as_uint(A[t       * 136 + rb + g + 8]);
            ah[mf][2] = __float_as_uint(A[(t + 4) * 136 + rb + g]);
            ah[mf][3] = __float_as_uint(A[(t + 4) * 136 + rb + g + 8]);
        }
        #pragma unroll
        for (int nf = 0; nf < 4; nf++) {
            int cb = wc * 4 + nf;
            float4 bf = *(const float4*)&B[(cb * 32 + lane) * 4];
            uint32_t bh[2] = {__float_as_uint(bf.x), __float_as_uint(bf.z)};
            uint32_t bl[2] = {__float_as_uint(bf.y), __float_as_uint(bf.w)};
            #pragma unroll
            for (int mf = 0; mf < 4; mf++) {
                mma_tf32(acc[mf][nf], ah[mf], bh);
                mma_tf32(acc[mf][nf], ah[mf], bl);
            }
        }
        __syncthreads();
    }

    #pragma unroll
    for (int mf = 0; mf < 4; mf++) {
        #pragma unroll
        for (int nf = 0; nf < 4; nf++) {
            int col = col0 + wc * 32 + nf * 8 + t * 2;
            #pragma unroll
            for (int rr = 0; rr < 2; rr++) {
                int row = row0 + wr * 64 + mf * 16 + g + rr * 8;
                float2* hp = (float2*)&g_h[(size_t)row * DCH + col];
                float2 hv = *hp;
                hv.x += acc[mf][nf][rr * 2];
                hv.y += acc[mf][nf][rr * 2 + 1];
                *hp = hv;
            }
        }
    }
}

// ---------------------------------------------------------------------------
// 1024-pt radix-4 Stockham FFT, 256 threads, ping-pong, result in y.
// ---------------------------------------------------------------------------
template<bool INV>
__device__ __forceinline__ void fft1024(float2* x, float2* y, const float2* tw, int tid)
{
    float2* src = x;
    float2* dst = y;
    #pragma unroll
    for (int s = 0; s < 5; s++) {
        int m = 1 << (2 * s);
        float2 c0 = src[tid];
        float2 c1 = src[tid + 256];
        float2 c2 = src[tid + 512];
        float2 c3 = src[tid + 768];
        float2 t0 = cadd(c0, c2);
        float2 t1 = csub(c0, c2);
        float2 t2 = cadd(c1, c3);
        float2 d  = csub(c1, c3);
        float2 t3 = INV ? make_float2(-d.y, d.x) : make_float2(d.y, -d.x);
        int jm = tid & ~(m - 1);
        float2 w1 = tw[jm];
        if (INV) w1.y = -w1.y;
        float2 w2 = cmul(w1, w1);
        float2 w3 = cmul(w2, w1);
        int base = tid + 3 * jm;
        dst[base]         = cadd(t0, t2);
        dst[base + m]     = cmul(w1, cadd(t1, t3));
        dst[base + 2 * m] = cmul(w2, csub(t0, t2));
        dst[base + 3 * m] = cmul(w3, csub(t1, t3));
        __syncthreads();
        float2* tmp = src; src = dst; dst = tmp;
    }
}

__global__ void fft_filt_kernel(const float* __restrict__ filt, int H)
{
    int h = blockIdx.x;
    int tid = threadIdx.x;
    __shared__ float2 bufA[1024];
    __shared__ float2 bufB[1024];
    __shared__ float2 tw[256];
    {
        float ang = -6.283185307179586f * (float)tid / 1024.f;
        float sn, cs;
        sincosf(ang, &sn, &cs);
        tw[tid] = make_float2(cs, sn);
    }
    for (int n = tid; n < 1024; n += 256)
        bufA[n] = make_float2(filt[(size_t)n * H + h], 0.f);
    __syncthreads();
    fft1024<false>(bufA, bufB, tw, tid);
    for (int f = tid; f < 1024; f += 256)
        g_Ff[h * 1024 + f] = bufB[f];
}

// Packed-pair conv; writes tf32-rounded result (A of gemm_out).
__global__ void conv_kernel(int H)
{
    int h = blockIdx.x;
    int b0 = blockIdx.y * 2, b1 = b0 + 1;
    int tid = threadIdx.x;
    __shared__ float2 bufA[1024];
    __shared__ float2 bufB[1024];
    __shared__ float2 tw[256];
    {
        float ang = -6.283185307179586f * (float)tid / 1024.f;
        float sn, cs;
        sincosf(ang, &sn, &cs);
        tw[tid] = make_float2(cs, sn);
    }

    const float* kv0 = &g_kv[((size_t)b0 * H + h) * NTOK];
    const float* kv1 = &g_kv[((size_t)b1 * H + h) * NTOK];
    float* qp0 = &g_q[((size_t)b0 * H + h) * NTOK];
    float* qp1 = &g_q[((size_t)b1 * H + h) * NTOK];

    {
        float4 u = *(const float4*)&kv0[tid * 4];
        float4 v = *(const float4*)&kv1[tid * 4];
        bufA[tid * 4 + 0] = make_float2(u.x, v.x);
        bufA[tid * 4 + 1] = make_float2(u.y, v.y);
        bufA[tid * 4 + 2] = make_float2(u.z, v.z);
        bufA[tid * 4 + 3] = make_float2(u.w, v.w);
    }
    __syncthreads();
    fft1024<false>(bufA, bufB, tw, tid);

    const float2* Fh = &g_Ff[h * 1024];
    for (int k = tid; k <= 512; k += 256) {
        int nk = (1024 - k) & 1023;
        float2 Z = bufB[k];
        float2 Y = bufB[nk];
        float Ar = 0.5f * (Z.x + Y.x), Ai = 0.5f * (Z.y - Y.y);
        float Br = 0.5f * (Z.y + Y.y), Bi = 0.5f * (Y.x - Z.x);
        float2 F = Fh[k];
        float P1r = Ar * F.x - Ai * F.y, P1i = Ar * F.y + Ai * F.x;
        float P2r = Br * F.x - Bi * F.y, P2i = Br * F.y + Bi * F.x;
        bufA[k] = make_float2(P1r - P2i, P1i + P2r);
        if (k != 0 && k != 512)
            bufA[nk] = make_float2(P1r + P2i, -P1i + P2r);
    }
    __syncthreads();
    fft1024<true>(bufA, bufB, tw, tid);

    const float inv = 1.f / 1024.f;
    {
        float4 q0 = *(const float4*)&qp0[tid * 4];
        float4 q1 = *(const float4*)&qp1[tid * 4];
        float2 c0 = bufB[tid * 4 + 0];
        float2 c1 = bufB[tid * 4 + 1];
        float2 c2 = bufB[tid * 4 + 2];
        float2 c3 = bufB[tid * 4 + 3];
        q0.x = tf32_rna_f(q0.x * c0.x * inv);
        q0.y = tf32_rna_f(q0.y * c1.x * inv);
        q0.z = tf32_rna_f(q0.z * c2.x * inv);
        q0.w = tf32_rna_f(q0.w * c3.x * inv);
        q1.x = tf32_rna_f(q1.x * c0.y * inv);
        q1.y = tf32_rna_f(q1.y * c1.y * inv);
        q1.z = tf32_rna_f(q1.z * c2.y * inv);
        q1.w = tf32_rna_f(q1.w * c3.y * inv);
        *(float4*)&qp0[tid * 4] = q0;
        *(float4*)&qp1[tid * 4] = q1;
    }
}

// ---------------------------------------------------------------------------
// reg_linear + BN partials: 32 tokens per block (4 batches of 8)
// ---------------------------------------------------------------------------
__global__ void __launch_bounds__(256) reglin_kernel(const float* __restrict__ Wm0,
                                                     const float* __restrict__ Wm1)
{
    __shared__ float W0[64 * 64];
    __shared__ float W1[64 * 64];
    __shared__ __align__(16) float hs[8 * 256];
    __shared__ float red0[256], red1[256];
    int tid = threadIdx.x;
    int row0 = blockIdx.x * 32;
    for (int i = tid; i < 4096; i += 256) { W0[i] = Wm0[i]; W1[i] = Wm1[i]; }
    int k = tid & 63, grp = tid >> 6;
    float ls0 = 0.f, ls1 = 0.f;
    for (int batch = 0; batch < 4; batch++) {
        __syncthreads();
        for (int i = tid; i < 2048; i += 256)
            hs[i] = g_h[(size_t)(row0 + batch * 8) * DCH + i];
        __syncthreads();
        #pragma unroll
        for (int tt = 0; tt < 2; tt++) {
            int t = grp * 2 + tt;
            const float* hr = &hs[t * 256];
            float s = 0.f, v0 = 0.f, v1 = 0.f, v2 = 0.f;
            #pragma unroll 8
            for (int m = 0; m < 64; m++) {
                float4 hv = *(const float4*)&hr[m * 4];
                float w0 = W0[m * 64 + k];
                float w1 = W1[m * 64 + k];
                s  += hv.x * w0;
                v0 += hv.y * w1;
                v1 += hv.z * w1;
                v2 += hv.w * w1;
            }
            *(float4*)&g_y[(size_t)(row0 + batch * 8 + t) * DCH + k * 4] = make_float4(s, v0, v1, v2);
            ls0 += s * s;
            ls1 += v0 * v0 + v1 * v1 + v2 * v2;
        }
    }
    red0[tid] = ls0; red1[tid] = ls1;
    __syncthreads();
    if (grp == 0) {
        float t0 = red0[k] + red0[64 + k] + red0[128 + k] + red0[192 + k];
        float t1 = red1[k] + red1[64 + k] + red1[128 + k] + red1[192 + k];
        g_part0[k * NBLK2 + blockIdx.x] = t0;
        g_part1[k * NBLK2 + blockIdx.x] = t1;
    }
}

__global__ void scale_red_kernel(const float* __restrict__ g0, const float* __restrict__ g1)
{
    int c = blockIdx.x;          // 0..127
    int ch = c & 63;
    const float* src = (c < 64) ? &g_part0[(size_t)ch * NBLK2] : &g_part1[(size_t)ch * NBLK2];
    int tid = threadIdx.x;
    float s = 0.f;
    for (int i = tid; i < NBLK2; i += 256) s += src[i];
    __shared__ float red[256];
    red[tid] = s;
    __syncthreads();
    for (int st = 128; st; st >>= 1) {
        if (tid < st) red[tid] += red[tid + st];
        __syncthreads();
    }
    if (tid == 0) {
        float norm = sqrtf(red[0] / (float)RTOT + EPSF);
        if (c < 64) g_scale0[ch] = g0[ch] / norm;
        else        g_scale1[ch] = g1[ch] / norm;
    }
}

__global__ void actres_kernel()
{
    size_t idx = (size_t)blockIdx.x * 256 + threadIdx.x;
    int m = (int)(idx & 63);
    float4 yv = *(float4*)&g_y[idx * 4];
    float s  = yv.x * g_scale0[m];
    float sc = g_scale1[m];
    float v0 = yv.y * sc, v1 = yv.z * sc, v2 = yv.w * sc;
    float sg  = 1.f / (1.f + __expf(-fabsf(s)));
    float vn  = sqrtf(v0 * v0 + v1 * v1 + v2 * v2 + EPSF);
    float sgv = 1.f / (1.f + __expf(-vn));
    float4* hp = (float4*)&g_h[idx * 4];
    float4 hv = *hp;
    hv.x += s * sg;
    hv.y += v0 * sgv;
    hv.z += v1 * sgv;
    hv.w += v2 * sgv;
    *hp = hv;
}

__global__ void pool_kernel(const float* __restrict__ w_out, float* __restrict__ out)
{
    int b = blockIdx.x;
    int tid = threadIdx.x;
    __shared__ float wsh[64];
    if (tid < 64) wsh[tid] = w_out[tid];
    __syncthreads();
    float a0 = 0.f, a1 = 0.f, a2 = 0.f;
    for (int n = tid; n < NTOK; n += 256) {
        const float* hr = &g_h[((size_t)b * NTOK + n) * DCH];
        #pragma unroll 8
        for (int m = 0; m < 64; m++) {
            float w = wsh[m];
            float4 hv = *(const float4*)&hr[m * 4];
            a0 += hv.y * w;
            a1 += hv.z * w;
            a2 += hv.w * w;
        }
    }
    __shared__ float r0[256], r1[256], r2[256];
    r0[tid] = a0; r1[tid] = a1; r2[tid] = a2;
    __syncthreads();
    for (int st = 128; st; st >>= 1) {
        if (tid < st) { r0[tid] += r0[tid + st]; r1[tid] += r1[tid + st]; r2[tid] += r2[tid + st]; }
        __syncthreads();
    }
    if (tid == 0) {
        out[b * 3 + 0] = r0[0] / (float)NTOK;
        out[b * 3 + 1] = r1[0] / (float)NTOK;
        out[b * 3 + 2] = r2[0] / (float)NTOK;
    }
}

// ---------------------------------------------------------------------------
extern "C" void kernel_launch(void* const* d_in, const int* in_sizes, int n_in,
                              void* d_out, int out_size)
{
    (void)in_sizes; (void)n_in; (void)out_size;
    const float* x       = (const float*)d_in[0];
    const float* tok_emb = (const float*)d_in[1];
    const float* Wf      = (const float*)d_in[2];
    const float* wv      = (const float*)d_in[3];
    const float* w_out   = (const float*)d_in[4];
    const int Hs[3] = {360, 360, 160};

    init_h_kernel<<<NTOK, 256>>>(x, tok_emb, Wf, wv);

    for (int L = 0; L < 3; L++) {
        int base = 5 + L * 9;
        const float* Wq   = (const float*)d_in[base + 0];
        const float* Wk   = (const float*)d_in[base + 1];
        const float* Wvw  = (const float*)d_in[base + 2];
        const float* filt = (const float*)d_in[base + 3];
        const float* Wo   = (const float*)d_in[base + 4];
        const float* Wm0  = (const float*)d_in[base + 5];
        const float* Wm1  = (const float*)d_in[base + 6];
        const float* g0   = (const float*)d_in[base + 7];
        const float* g1   = (const float*)d_in[base + 8];
        int H = Hs[L];

        presplit_qkv<<<DCH * HPAD / 256, 256>>>(Wq, Wk, Wvw, H);
        presplit_wo<<<HPAD * DCH / 256, 256>>>(Wo, H);
        gemm_qkv<<<dim3((H + 63) / 64, RTOT / 128), 256>>>(H);
        fft_filt_kernel<<<H, 256>>>(filt, H);
        conv_kernel<<<dim3(H, BSZ / 2), 256>>>(H);
        gemm_out<<<dim3(DCH / 128, RTOT / 128), 256>>>(H);
        reglin_kernel<<<NBLK2, 256>>>(Wm0, Wm1);
        scale_red_kernel<<<128, 256>>>(g0, g1);
        actres_kernel<<<RTOT * 64 / 256, 256>>>();
    }

    pool_kernel<<<BSZ, 256>>>(w_out, (float*)d_out);
}

// round 6
// speedup vs baseline: 1.9858x; 1.0375x over previous
#include <cuda_runtime.h>
#include <math.h>
#include <stdint.h>

// Problem constants
#define BSZ   64
#define NTOK  1024
#define MCH   64
#define DCH   256       // 4*M
#define PDIM  64
#define RTOT  (BSZ*NTOK)   // 65536
#define HMAX  360
#define HPADMAX 384
#define EPSF  1e-5f
#define NBLK2 (RTOT/32)    // 2048 reglin blocks

// -------- scratch (static __device__ globals) --------
__device__ __align__(16) float g_h[(size_t)RTOT*DCH];
__device__ __align__(16) float g_y[(size_t)RTOT*DCH];
__device__ __align__(16) float g_q[(size_t)BSZ*HMAX*NTOK];
__device__ __align__(16) float g_k[(size_t)BSZ*HMAX*NTOK];
__device__ __align__(16) float g_v[(size_t)BSZ*HMAX*NTOK];
__device__ __align__(16) float2 g_Ff[HMAX*NTOK];
// fragment-packed concatenated qkv weights: [kb][cb][lane][4] (b0h,b0l,b1h,b1l)
__device__ __align__(16) float g_WcF[32][3*HPADMAX/8][32][4];
__device__ __align__(16) float g_WoF[HPADMAX/8][32][32][4];
__device__ float g_part0[MCH*NBLK2];
__device__ float g_part1[MCH*NBLK2];
__device__ float g_scale0[MCH];
__device__ float g_scale1[MCH];

// ---------------------------------------------------------------------------
__device__ __forceinline__ void mma_tf32(float* c, const uint32_t* a, const uint32_t* b)
{
    asm volatile(
        "mma.sync.aligned.m16n8k8.row.col.f32.tf32.tf32.f32 "
        "{%0,%1,%2,%3}, {%4,%5,%6,%7}, {%8,%9}, {%0,%1,%2,%3};\n"
        : "+f"(c[0]), "+f"(c[1]), "+f"(c[2]), "+f"(c[3])
        : "r"(a[0]), "r"(a[1]), "r"(a[2]), "r"(a[3]), "r"(b[0]), "r"(b[1]));
}

__device__ __forceinline__ float tf32_rna_f(float x)
{
    uint32_t r;
    asm("cvt.rna.tf32.f32 %0, %1;" : "=r"(r) : "f"(x));
    return __uint_as_float(r);
}
__device__ __forceinline__ uint32_t rna_bits(float x)
{
    uint32_t r;
    asm("cvt.rna.tf32.f32 %0, %1;" : "=r"(r) : "f"(x));
    return r;
}

__device__ __forceinline__ uint32_t sAddr(const void* p)
{
    return (uint32_t)__cvta_generic_to_shared(p);
}
__device__ __forceinline__ void cp16(uint32_t dst, const void* src)
{
    asm volatile("cp.async.cg.shared.global [%0], [%1], 16;\n" :: "r"(dst), "l"(src));
}
#define CP_COMMIT() asm volatile("cp.async.commit_group;\n")
#define CP_WAIT1()  asm volatile("cp.async.wait_group 1;\n")
#define CP_WAIT0()  asm volatile("cp.async.wait_group 0;\n")

__device__ __forceinline__ float2 cmul(float2 a, float2 b)
{ return make_float2(a.x*b.x - a.y*b.y, a.x*b.y + a.y*b.x); }
__device__ __forceinline__ float2 cadd(float2 a, float2 b){ return make_float2(a.x+b.x, a.y+b.y); }
__device__ __forceinline__ float2 csub(float2 a, float2 b){ return make_float2(a.x-b.x, a.y-b.y); }

// ---------------------------------------------------------------------------
// init h
// ---------------------------------------------------------------------------
__global__ void init_h_kernel(const float* __restrict__ x,
                              const float* __restrict__ tok_emb,
                              const float* __restrict__ Wf,
                              const float* __restrict__ wv)
{
    int n = blockIdx.x;
    int tid = threadIdx.x;   // 256
    __shared__ float f[PDIM];
    __shared__ float s0[MCH];
    if (tid < PDIM) {
        int p = tid;
        int j2 = p & ~1;
        float div = expf(-logf(10000.0f) * (float)j2 / (float)PDIM);
        float ang = (float)n * div;
        float pe = (p & 1) ? cosf(ang) : sinf(ang);
        int tt = (n == NTOK - 1) ? 2 : (n & 1);
        f[p] = pe + tok_emb[tt * PDIM + p];
    }
    __syncthreads();
    if (tid < MCH) {
        float acc = 0.f;
        #pragma unroll 8
        for (int p = 0; p < PDIM; p++) acc += f[p] * Wf[p * MCH + tid];
        s0[tid] = acc;
    }
    __syncthreads();
    int m = tid >> 2, r = tid & 3;
    float wvm = wv[m];
    float sv = s0[m];
    for (int b = 0; b < BSZ; b++) {
        float val;
        if (r == 0) val = sv;
        else        val = x[((size_t)b * NTOK + n) * 3 + (r - 1)] * wvm;
        g_h[((size_t)b * NTOK + n) * DCH + tid] = val;
    }
}

// ---------------------------------------------------------------------------
// weight pre-split: concatenated [Wq|Wk|Wv] (each padded to HP) into
// fragment-packed g_WcF; Wo into g_WoF.
// ---------------------------------------------------------------------------
template<int HP>
__global__ void presplit_cat(const float* __restrict__ Wq,
                             const float* __restrict__ Wk,
                             const float* __restrict__ Wv2, int H)
{
    int idx = blockIdx.x * 256 + threadIdx.x;   // over 256 * 3*HP
    int k = idx / (3 * HP), c = idx % (3 * HP);
    int mat = c / HP, h = c % HP;
    int kb = k >> 3, kk = k & 7;
    int t = kk & 3, pos = kk >> 2;
    int cb = c >> 3, lane = (c & 7) * 4 + t;
    const float* W = (mat == 0) ? Wq : (mat == 1) ? Wk : Wv2;
    float w = (h < H) ? W[(size_t)k * H + h] : 0.f;
    float hi = tf32_rna_f(w);
    g_WcF[kb][cb][lane][pos * 2]     = hi;
    g_WcF[kb][cb][lane][pos * 2 + 1] = w - hi;
}

__global__ void presplit_wo(const float* __restrict__ Wo, int H)
{
    int idx = blockIdx.x * 256 + threadIdx.x;   // over HPADMAX*256
    int k = idx >> 8, n = idx & 255;
    int kb = k >> 3, kk = k & 7;
    int t = kk & 3, pos = kk >> 2;
    int cb = n >> 3, lane = (n & 7) * 4 + t;
    float w = (k < H) ? Wo[(size_t)k * DCH + n] : 0.f;
    float hi = tf32_rna_f(w);
    g_WoF[kb][cb][lane][pos * 2]     = hi;
    g_WoF[kb][cb][lane][pos * 2 + 1] = w - hi;
}

// ---------------------------------------------------------------------------
// Merged qkv GEMM: C[R, 3*HP] = A[R,256] @ Wcat. Tile 128x128, kstep 8,
// 3-stage cp.async ring, one sync per kstep. Warps 2m x 4n, warp tile 64x32.
// Writes Q, K, V each in [B,H,N] layout.
// ---------------------------------------------------------------------------
template<int HP>
__global__ void __launch_bounds__(256, 2) gemm_in(int H)
{
    __shared__ __align__(16) float shA[3][128 * 12];
    __shared__ __align__(16) float shB[3][16 * 32 * 4];

    int tid = threadIdx.x;
    int row0 = blockIdx.y * 128;
    int col0 = blockIdx.x * 128;        // over 3*HP
    int b = row0 >> 10;
    int nbase = row0 & (NTOK - 1);
    int cb0 = col0 >> 3;                // 16 cbs per block

    int wid = tid >> 5, lane = tid & 31;
    int g = lane >> 2, t = lane & 3;
    int wr = wid >> 2, wc = wid & 3;

    float acc[4][4][4] = {};

    int ar = tid >> 1, ahalf = tid & 1;
    const float* aSrc = &g_h[(size_t)(row0 + ar) * DCH + ahalf * 4];

    #define IN_LOAD(kb, st)                                                   \
    {                                                                         \
        cp16(sAddr(&shA[st][ar * 12 + ahalf * 4]), aSrc + (kb) * 8);          \
        _Pragma("unroll")                                                     \
        for (int i = 0; i < 2; i++) {                                         \
            int c = i * 256 + tid;                                            \
            int cb = c >> 5, ln = c & 31;                                     \
            cp16(sAddr(&shB[st][(cb * 32 + ln) * 4]),                         \
                 &g_WcF[kb][cb0 + cb][ln][0]);                                \
        }                                                                     \
        CP_COMMIT();                                                          \
    }

    IN_LOAD(0, 0);
    IN_LOAD(1, 1);

    for (int kb = 0; kb < 32; kb++) {
        if (kb == 31) { CP_WAIT0(); } else { CP_WAIT1(); }
        __syncthreads();
        int st = kb % 3;
        const float* A = shA[st];
        const float* B = shB[st];

        uint32_t ah[4][4];
        #pragma unroll
        for (int mf = 0; mf < 4; mf++) {
            int rb = wr * 64 + mf * 16;
            ah[mf][0] = rna_bits(A[(rb + g)     * 12 + t]);
            ah[mf][1] = rna_bits(A[(rb + g + 8) * 12 + t]);
            ah[mf][2] = rna_bits(A[(rb + g)     * 12 + t + 4]);
            ah[mf][3] = rna_bits(A[(rb + g + 8) * 12 + t + 4]);
        }
        #pragma unroll
        for (int nf = 0; nf < 4; nf++) {
            int cb = wc * 4 + nf;
            float4 bf = *(const float4*)&B[(cb * 32 + lane) * 4];
            uint32_t bh[2] = {__float_as_uint(bf.x), __float_as_uint(bf.z)};
            uint32_t bl[2] = {__float_as_uint(bf.y), __float_as_uint(bf.w)};
            #pragma unroll
            for (int mf = 0; mf < 4; mf++) {
                mma_tf32(acc[mf][nf], ah[mf], bh);
                mma_tf32(acc[mf][nf], ah[mf], bl);
            }
        }
        if (kb + 2 < 32) {
            int kn = kb + 2;
            IN_LOAD(kn, kn % 3);
        }
    }
    #undef IN_LOAD

    // epilogue: route each column to Q/K/V
    #pragma unroll
    for (int mf = 0; mf < 4; mf++) {
        #pragma unroll
        for (int nf = 0; nf < 4; nf++) {
            #pragma unroll
            for (int cc = 0; cc < 2; cc++) {
                int col = col0 + wc * 32 + nf * 8 + t * 2 + cc;
                int mat = col / HP;
                int hcol = col - mat * HP;
                if (hcol < H) {
                    float* dst = (mat == 0) ? g_q : (mat == 1) ? g_k : g_v;
                    size_t base = ((size_t)b * H + hcol) * NTOK + nbase + wr * 64 + mf * 16 + g;
                    dst[base]     = acc[mf][nf][cc];
                    dst[base + 8] = acc[mf][nf][cc + 2];
                }
            }
        }
    }
}

// ---------------------------------------------------------------------------
// Wo GEMM + residual: g_h[R,256] += G[R,H] @ Wo[H,256].
// Tile 128x128, kstep 8, 3-stage ring, one sync per kstep.
// ---------------------------------------------------------------------------
__global__ void __launch_bounds__(256, 2) gemm_out(int H)
{
    __shared__ __align__(16) float shA[3][8 * 136];
    __shared__ __align__(16) float shB[3][16 * 32 * 4];

    int tid = threadIdx.x;
    int row0 = blockIdx.y * 128;
    int col0 = blockIdx.x * 128;
    int b = row0 >> 10;
    int nbase = row0 & (NTOK - 1);
    int cb0 = col0 >> 3;

    int wid = tid >> 5, lane = tid & 31;
    int g = lane >> 2, t = lane & 3;
    int wr = wid >> 2, wc = wid & 3;

    float acc[4][4][4] = {};

    int akk = tid >> 5, aseg = tid & 31;
    const float* aRow = &g_q[((size_t)b * H + akk) * NTOK + nbase + aseg * 4];
    size_t aStride = (size_t)8 * NTOK;

    #define OUT_LOAD(kb, st)                                                     \
    {                                                                            \
        cp16(sAddr(&shA[st][akk * 136 + aseg * 4]), aRow + (size_t)(kb) * aStride); \
        _Pragma("unroll")                                                        \
        for (int i = 0; i < 2; i++) {                                            \
            int c = i * 256 + tid;                                               \
            int cb = c >> 5, ln = c & 31;                                        \
            cp16(sAddr(&shB[st][(cb * 32 + ln) * 4]),                            \
                 &g_WoF[kb][cb0 + cb][ln][0]);                                   \
        }                                                                        \
        CP_COMMIT();                                                             \
    }

    int ksteps = H >> 3;   // 45 or 20 (exact)
    OUT_LOAD(0, 0);
    OUT_LOAD(1, 1);

    for (int kb = 0; kb < ksteps; kb++) {
        if (kb == ksteps - 1) { CP_WAIT0(); } else { CP_WAIT1(); }
        __syncthreads();
        int st = kb % 3;
        const float* A = shA[st];
        const float* B = shB[st];

        uint32_t ah[4][4];
        #pragma unroll
        for (int mf = 0; mf < 4; mf++) {
            int rb = wr * 64 + mf * 16;
            ah[mf][0] = __float_as_uint(A[t       * 136 + rb + g]);
            ah[mf][1] = __float_as_uint(A[t       * 136 + rb + g + 8]);
            ah[mf][2] = __float_as_uint(A[(t + 4) * 136 + rb + g]);
            ah[mf][3] = __float_as_uint(A[(t + 4) * 136 + rb + g + 8]);
        }
        #pragma unroll
        for (int nf = 0; nf < 4; nf++) {
            int cb = wc * 4 + nf;
            float4 bf = *(const float4*)&B[(cb * 32 + lane) * 4];
            uint32_t bh[2] = {__float_as_uint(bf.x), __float_as_uint(bf.z)};
            uint32_t bl[2] = {__float_as_uint(bf.y), __float_as_uint(bf.w)};
            #pragma unroll
            for (int mf = 0; mf < 4; mf++) {
                mma_tf32(acc[mf][nf], ah[mf], bh);
                mma_tf32(acc[mf][nf], ah[mf], bl);
            }
        }
        if (kb + 2 < ksteps) {
            int kn = kb + 2;
            OUT_LOAD(kn, kn % 3);
        }
    }
    #undef OUT_LOAD

    #pragma unroll
    for (int mf = 0; mf < 4; mf++) {
        #pragma unroll
        for (int nf = 0; nf < 4; nf++) {
            int col = col0 + wc * 32 + nf * 8 + t * 2;
            #pragma unroll
            for (int rr = 0; rr < 2; rr++) {
                int row = row0 + wr * 64 + mf * 16 + g + rr * 8;
                float2* hp = (float2*)&g_h[(size_t)row * DCH + col];
                float2 hv = *hp;
                hv.x += acc[mf][nf][rr * 2];
                hv.y += acc[mf][nf][rr * 2 + 1];
                *hp = hv;
            }
        }
    }
}

// ---------------------------------------------------------------------------
// 1024-pt radix-4 Stockham FFT, 256 threads, ping-pong, result in y.
// ---------------------------------------------------------------------------
template<bool INV>
__device__ __forceinline__ void fft1024(float2* x, float2* y, const float2* tw, int tid)
{
    float2* src = x;
    float2* dst = y;
    #pragma unroll
    for (int s = 0; s < 5; s++) {
        int m = 1 << (2 * s);
        float2 c0 = src[tid];
        float2 c1 = src[tid + 256];
        float2 c2 = src[tid + 512];
        float2 c3 = src[tid + 768];
        float2 t0 = cadd(c0, c2);
        float2 t1 = csub(c0, c2);
        float2 t2 = cadd(c1, c3);
        float2 d  = csub(c1, c3);
        float2 t3 = INV ? make_float2(-d.y, d.x) : make_float2(d.y, -d.x);
        int jm = tid & ~(m - 1);
        float2 w1 = tw[jm];
        if (INV) w1.y = -w1.y;
        float2 w2 = cmul(w1, w1);
        float2 w3 = cmul(w2, w1);
        int base = tid + 3 * jm;
        dst[base]         = cadd(t0, t2);
        dst[base + m]     = cmul(w1, cadd(t1, t3));
        dst[base + 2 * m] = cmul(w2, csub(t0, t2));
        dst[base + 3 * m] = cmul(w3, csub(t1, t3));
        __syncthreads();
        float2* tmp = src; src = dst; dst = tmp;
    }
}

__global__ void fft_filt_kernel(const float* __restrict__ filt, int H)
{
    int h = blockIdx.x;
    int tid = threadIdx.x;
    __shared__ float2 bufA[1024];
    __shared__ float2 bufB[1024];
    __shared__ float2 tw[256];
    {
        float ang = -6.283185307179586f * (float)tid / 1024.f;
        float sn, cs;
        sincosf(ang, &sn, &cs);
        tw[tid] = make_float2(cs, sn);
    }
    for (int n = tid; n < 1024; n += 256)
        bufA[n] = make_float2(filt[(size_t)n * H + h], 0.f);
    __syncthreads();
    fft1024<false>(bufA, bufB, tw, tid);
    for (int f = tid; f < 1024; f += 256)
        g_Ff[h * 1024 + f] = bufB[f];
}

// Packed-pair conv; computes kv = k*v at load; writes tf32-rounded result.
__global__ void conv_kernel(int H)
{
    int h = blockIdx.x;
    int b0 = blockIdx.y * 2, b1 = b0 + 1;
    int tid = threadIdx.x;
    __shared__ float2 bufA[1024];
    __shared__ float2 bufB[1024];
    __shared__ float2 tw[256];
    {
        float ang = -6.283185307179586f * (float)tid / 1024.f;
        float sn, cs;
        sincosf(ang, &sn, &cs);
        tw[tid] = make_float2(cs, sn);
    }

    const float* k0 = &g_k[((size_t)b0 * H + h) * NTOK];
    const float* k1 = &g_k[((size_t)b1 * H + h) * NTOK];
    const float* v0 = &g_v[((size_t)b0 * H + h) * NTOK];
    const float* v1 = &g_v[((size_t)b1 * H + h) * NTOK];
    float* qp0 = &g_q[((size_t)b0 * H + h) * NTOK];
    float* qp1 = &g_q[((size_t)b1 * H + h) * NTOK];

    {
        float4 ka = *(const float4*)&k0[tid * 4];
        float4 va = *(const float4*)&v0[tid * 4];
        float4 kb = *(const float4*)&k1[tid * 4];
        float4 vb = *(const float4*)&v1[tid * 4];
        bufA[tid * 4 + 0] = make_float2(ka.x * va.x, kb.x * vb.x);
        bufA[tid * 4 + 1] = make_float2(ka.y * va.y, kb.y * vb.y);
        bufA[tid * 4 + 2] = make_float2(ka.z * va.z, kb.z * vb.z);
        bufA[tid * 4 + 3] = make_float2(ka.w * va.w, kb.w * vb.w);
    }
    __syncthreads();
    fft1024<false>(bufA, bufB, tw, tid);

    const float2* Fh = &g_Ff[h * 1024];
    for (int k = tid; k <= 512; k += 256) {
        int nk = (1024 - k) & 1023;
        float2 Z = bufB[k];
        float2 Y = bufB[nk];
        float Ar = 0.5f * (Z.x + Y.x), Ai = 0.5f * (Z.y - Y.y);
        float Br = 0.5f * (Z.y + Y.y), Bi = 0.5f * (Y.x - Z.x);
        float2 F = Fh[k];
        float P1r = Ar * F.x - Ai * F.y, P1i = Ar * F.y + Ai * F.x;
        float P2r = Br * F.x - Bi * F.y, P2i = Br * F.y + Bi * F.x;
        bufA[k] = make_float2(P1r - P2i, P1i + P2r);
        if (k != 0 && k != 512)
            bufA[nk] = make_float2(P1r + P2i, -P1i + P2r);
    }
    __syncthreads();
    fft1024<true>(bufA, bufB, tw, tid);

    const float inv = 1.f / 1024.f;
    {
        float4 q0 = *(const float4*)&qp0[tid * 4];
        float4 q1 = *(const float4*)&qp1[tid * 4];
        float2 c0 = bufB[tid * 4 + 0];
        float2 c1 = bufB[tid * 4 + 1];
        float2 c2 = bufB[tid * 4 + 2];
        float2 c3 = bufB[tid * 4 + 3];
        q0.x = tf32_rna_f(q0.x * c0.x * inv);
        q0.y = tf32_rna_f(q0.y * c1.x * inv);
        q0.z = tf32_rna_f(q0.z * c2.x * inv);
        q0.w = tf32_rna_f(q0.w * c3.x * inv);
        q1.x = tf32_rna_f(q1.x * c0.y * inv);
        q1.y = tf32_rna_f(q1.y * c1.y * inv);
        q1.z = tf32_rna_f(q1.z * c2.y * inv);
        q1.w = tf32_rna_f(q1.w * c3.y * inv);
        *(float4*)&qp0[tid * 4] = q0;
        *(float4*)&qp1[tid * 4] = q1;
    }
}

// ---------------------------------------------------------------------------
// reg_linear + BN partials: 32 tokens per block
// ---------------------------------------------------------------------------
__global__ void __launch_bounds__(256) reglin_kernel(const float* __restrict__ Wm0,
                                                     const float* __restrict__ Wm1)
{
    __shared__ float W0[64 * 64];
    __shared__ float W1[64 * 64];
    __shared__ __align__(16) float hs[8 * 256];
    __shared__ float red0[256], red1[256];
    int tid = threadIdx.x;
    int row0 = blockIdx.x * 32;
    for (int i = tid; i < 4096; i += 256) { W0[i] = Wm0[i]; W1[i] = Wm1[i]; }
    int k = tid & 63, grp = tid >> 6;
    float ls0 = 0.f, ls1 = 0.f;
    for (int batch = 0; batch < 4; batch++) {
        __syncthreads();
        for (int i = tid; i < 2048; i += 256)
            hs[i] = g_h[(size_t)(row0 + batch * 8) * DCH + i];
        __syncthreads();
        #pragma unroll
        for (int tt = 0; tt < 2; tt++) {
            int t = grp * 2 + tt;
            const float* hr = &hs[t * 256];
            float s = 0.f, v0 = 0.f, v1 = 0.f, v2 = 0.f;
            #pragma unroll 8
            for (int m = 0; m < 64; m++) {
                float4 hv = *(const float4*)&hr[m * 4];
                float w0 = W0[m * 64 + k];
                float w1 = W1[m * 64 + k];
                s  += hv.x * w0;
                v0 += hv.y * w1;
                v1 += hv.z * w1;
                v2 += hv.w * w1;
            }
            *(float4*)&g_y[(size_t)(row0 + batch * 8 + t) * DCH + k * 4] = make_float4(s, v0, v1, v2);
            ls0 += s * s;
            ls1 += v0 * v0 + v1 * v1 + v2 * v2;
        }
    }
    red0[tid] = ls0; red1[tid] = ls1;
    __syncthreads();
    if (grp == 0) {
        float t0 = red0[k] + red0[64 + k] + red0[128 + k] + red0[192 + k];
        float t1 = red1[k] + red1[64 + k] + red1[128 + k] + red1[192 + k];
        g_part0[k * NBLK2 + blockIdx.x] = t0;
        g_part1[k * NBLK2 + blockIdx.x] = t1;
    }
}

__global__ void scale_red_kernel(const float* __restrict__ g0, const float* __restrict__ g1)
{
    int c = blockIdx.x;          // 0..127
    int ch = c & 63;
    const float* src = (c < 64) ? &g_part0[(size_t)ch * NBLK2] : &g_part1[(size_t)ch * NBLK2];
    int tid = threadIdx.x;
    float s = 0.f;
    for (int i = tid; i < NBLK2; i += 256) s += src[i];
    __shared__ float red[256];
    red[tid] = s;
    __syncthreads();
    for (int st = 128; st; st >>= 1) {
        if (tid < st) red[tid] += red[tid + st];
        __syncthreads();
    }
    if (tid == 0) {
        float norm = sqrtf(red[0] / (float)RTOT + EPSF);
        if (c < 64) g_scale0[ch] = g0[ch] / norm;
        else        g_scale1[ch] = g1[ch] / norm;
    }
}

__global__ void actres_kernel()
{
    size_t idx = (size_t)blockIdx.x * 256 + threadIdx.x;
    int m = (int)(idx & 63);
    float4 yv = *(float4*)&g_y[idx * 4];
    float s  = yv.x * g_scale0[m];
    float sc = g_scale1[m];
    float v0 = yv.y * sc, v1 = yv.z * sc, v2 = yv.w * sc;
    float sg  = 1.f / (1.f + __expf(-fabsf(s)));
    float vn  = sqrtf(v0 * v0 + v1 * v1 + v2 * v2 + EPSF);
    float sgv = 1.f / (1.f + __expf(-vn));
    float4* hp = (float4*)&g_h[idx * 4];
    float4 hv = *hp;
    hv.x += s * sg;
    hv.y += v0 * sgv;
    hv.z += v1 * sgv;
    hv.w += v2 * sgv;
    *hp = hv;
}

__global__ void pool_kernel(const float* __restrict__ w_out, float* __restrict__ out)
{
    int b = blockIdx.x;
    int tid = threadIdx.x;
    __shared__ float wsh[64];
    if (tid < 64) wsh[tid] = w_out[tid];
    __syncthreads();
    float a0 = 0.f, a1 = 0.f, a2 = 0.f;
    for (int n = tid; n < NTOK; n += 256) {
        const float* hr = &g_h[((size_t)b * NTOK + n) * DCH];
        #pragma unroll 8
        for (int m = 0; m < 64; m++) {
            float w = wsh[m];
            float4 hv = *(const float4*)&hr[m * 4];
            a0 += hv.y * w;
            a1 += hv.z * w;
            a2 += hv.w * w;
        }
    }
    __shared__ float r0[256], r1[256], r2[256];
    r0[tid] = a0; r1[tid] = a1; r2[tid] = a2;
    __syncthreads();
    for (int st = 128; st; st >>= 1) {
        if (tid < st) { r0[tid] += r0[tid + st]; r1[tid] += r1[tid + st]; r2[tid] += r2[tid + st]; }
        __syncthreads();
    }
    if (tid == 0) {
        out[b * 3 + 0] = r0[0] / (float)NTOK;
        out[b * 3 + 1] = r1[0] / (float)NTOK;
        out[b * 3 + 2] = r2[0] / (float)NTOK;
    }
}

// ---------------------------------------------------------------------------
extern "C" void kernel_launch(void* const* d_in, const int* in_sizes, int n_in,
                              void* d_out, int out_size)
{
    (void)in_sizes; (void)n_in; (void)out_size;
    const float* x       = (const float*)d_in[0];
    const float* tok_emb = (const float*)d_in[1];
    const float* Wf      = (const float*)d_in[2];
    const float* wv      = (const float*)d_in[3];
    const float* w_out   = (const float*)d_in[4];
    const int Hs[3] = {360, 360, 160};

    init_h_kernel<<<NTOK, 256>>>(x, tok_emb, Wf, wv);

    for (int L = 0; L < 3; L++) {
        int base = 5 + L * 9;
        const float* Wq   = (const float*)d_in[base + 0];
        const float* Wk   = (const float*)d_in[base + 1];
        const float* Wvw  = (const float*)d_in[base + 2];
        const float* filt = (const float*)d_in[base + 3];
        const float* Wo   = (const float*)d_in[base + 4];
        const float* Wm0  = (const float*)d_in[base + 5];
        const float* Wm1  = (const float*)d_in[base + 6];
        const float* g0   = (const float*)d_in[base + 7];
        const float* g1   = (const float*)d_in[base + 8];
        int H = Hs[L];

        if (H > 256) {
            presplit_cat<384><<<256 * 3 * 384 / 256, 256>>>(Wq, Wk, Wvw, H);
            gemm_in<384><<<dim3(3 * 384 / 128, RTOT / 128), 256>>>(H);
        } else {
            presplit_cat<256><<<256 * 3 * 256 / 256, 256>>>(Wq, Wk, Wvw, H);
            gemm_in<256><<<dim3(3 * 256 / 128, RTOT / 128), 256>>>(H);
        }
        presplit_wo<<<HPADMAX * DCH / 256, 256>>>(Wo, H);
        fft_filt_kernel<<<H, 256>>>(filt, H);
        conv_kernel<<<dim3(H, BSZ / 2), 256>>>(H);
        gemm_out<<<dim3(DCH / 128, RTOT / 128), 256>>>(H);
        reglin_kernel<<<NBLK2, 256>>>(Wm0, Wm1);
        scale_red_kernel<<<128, 256>>>(g0, g1);
        actres_kernel<<<RTOT * 64 / 256, 256>>>();
    }

    pool_kernel<<<BSZ, 256>>>(w_out, (float*)d_out);
}